// round 4
// baseline (speedup 1.0000x reference)
#include <cuda_runtime.h>
#include <math.h>

// Problem dims (fixed instance)
#define B_   2
#define N_   2048
#define D_   768
#define H_   12
#define DH_  64
#define M_   3072
#define R_   (B_*N_)          // 4096 token rows
#define QKVC (3*H_*DH_)       // 2304

// ---------------- scratch (device globals; no allocations allowed) ---------
__device__ float g_h[(size_t)R_*D_];
__device__ float g_qkv[(size_t)R_*QKVC];
__device__ float g_attnout[(size_t)R_*D_];
__device__ float g_x1[(size_t)R_*D_];
__device__ float g_ffn[(size_t)R_*M_];

// ---------------- helpers ---------------------------------------------------
__device__ __forceinline__ void cpa16(void* dst, const void* src){
    unsigned d = (unsigned)__cvta_generic_to_shared(dst);
    asm volatile("cp.async.cg.shared.global [%0], [%1], 16;\n" :: "r"(d), "l"(src));
}
__device__ __forceinline__ void cpa4(void* dst, const void* src){
    unsigned d = (unsigned)__cvta_generic_to_shared(dst);
    asm volatile("cp.async.ca.shared.global [%0], [%1], 4;\n" :: "r"(d), "l"(src));
}
// raw fp32 bits into tf32 mma (HW uses upper 19 bits; RZ truncation)
__device__ __forceinline__ void mma_tf32(float* c, const unsigned* a, unsigned b0, unsigned b1){
    asm volatile("mma.sync.aligned.m16n8k8.row.col.f32.tf32.tf32.f32 "
        "{%0,%1,%2,%3}, {%4,%5,%6,%7}, {%8,%9}, {%0,%1,%2,%3};\n"
        : "+f"(c[0]),"+f"(c[1]),"+f"(c[2]),"+f"(c[3])
        : "r"(a[0]),"r"(a[1]),"r"(a[2]),"r"(a[3]), "r"(b0),"r"(b1));
}

// ---------------- LayerNorm: one block (256 thr) per row of 768 ------------
__global__ void ln_kernel(const float* __restrict__ x,
                          const float* __restrict__ gamma,
                          const float* __restrict__ beta,
                          float* __restrict__ out)
{
    const int row = blockIdx.x;
    const float* xr = x + (long)row * D_;
    float v[3];
    float s = 0.f, s2 = 0.f;
    #pragma unroll
    for (int i = 0; i < 3; i++) {
        v[i] = xr[threadIdx.x + i*256];
        s  += v[i];
        s2 += v[i]*v[i];
    }
    #pragma unroll
    for (int o = 16; o > 0; o >>= 1) {
        s  += __shfl_xor_sync(0xffffffffu, s,  o);
        s2 += __shfl_xor_sync(0xffffffffu, s2, o);
    }
    __shared__ float sa[8], sb[8];
    int w = threadIdx.x >> 5, l = threadIdx.x & 31;
    if (l == 0) { sa[w] = s; sb[w] = s2; }
    __syncthreads();
    s = 0.f; s2 = 0.f;
    #pragma unroll
    for (int i = 0; i < 8; i++) { s += sa[i]; s2 += sb[i]; }

    const float mean = s * (1.0f / D_);
    const float var  = s2 * (1.0f / D_) - mean*mean;
    const float rstd = rsqrtf(var + 1e-5f);
    float* o = out + (long)row * D_;
    #pragma unroll
    for (int i = 0; i < 3; i++) {
        int c = threadIdx.x + i*256;
        o[c] = (v[i] - mean) * rstd * gamma[c] + beta[c];
    }
}

// ---------------- Flash attention -------------------------------------------
// softmax(QK^T*scale + bias) @ V, fused.  128 q-rows per block, 8 warps.
// K and Q stored in permuted layout: element (r,c) at r*80 + (c&3)*20 + (c>>2)
// so each thread's fragment data is contiguous (LDS.128, conflict-free).
#define KJ  80
#define VST 72
#define PST 132
#define KBUF (128*KJ)
#define VBUF (128*VST)
#define VS_OFF (2*KBUF)
#define PS_OFF (2*KBUF + 2*VBUF)
#define FA_SMEM ((2*KBUF + 2*VBUF + 128*PST)*4)

__global__ void __launch_bounds__(256,1)
flash_kernel(const float* __restrict__ qkv,
             const float* __restrict__ bias,
             float* __restrict__ ao)
{
    extern __shared__ float sm[];
    float* Ks = sm;
    float* Vs = sm + VS_OFF;
    float* Ps = sm + PS_OFF;

    const int qt = blockIdx.x;       // 0..15
    const int hh = blockIdx.y;       // 0..11
    const int bb = blockIdx.z;       // 0..1
    const int q0 = qt*128;
    const long base = (long)bb*N_*QKVC;
    const float* Qg = qkv + base + hh*DH_;
    const float* Kg = qkv + base + H_*DH_ + hh*DH_;
    const float* Vg = qkv + base + 2*H_*DH_ + hh*DH_;
    const float* Bg = bias + (long)hh*N_*N_;

    const int tid = threadIdx.x, wid = tid>>5, lane = tid&31;
    const int g = lane>>2, tg = lane&3;
    const int mrow = wid*16;

    // prologue: group0 = {Q(perm), K0(perm), V0}, group1 = {K1(perm), V1}
    {
        #pragma unroll
        for (int it = 0; it < 32; it++){
            int i = tid + it*256;
            int r = i >> 6, c = i & 63;
            int pj = (c&3)*20 + (c>>2);
            cpa4(&Ps[r*KJ + pj], &Qg[(long)(q0+r)*QKVC + c]);
            cpa4(&Ks[r*KJ + pj], &Kg[(long)r*QKVC + c]);
        }
        #pragma unroll
        for (int it = 0; it < 8; it++){
            int i = tid + it*256;
            int r = i >> 4, c4 = (i & 15)*4;
            cpa16(&Vs[r*VST + c4], &Vg[(long)r*QKVC + c4]);
        }
        asm volatile("cp.async.commit_group;\n");
        #pragma unroll
        for (int it = 0; it < 32; it++){
            int i = tid + it*256;
            int r = i >> 6, c = i & 63;
            int pj = (c&3)*20 + (c>>2);
            cpa4(&Ks[KBUF + r*KJ + pj], &Kg[(long)(128+r)*QKVC + c]);
        }
        #pragma unroll
        for (int it = 0; it < 8; it++){
            int i = tid + it*256;
            int r = i >> 4, c4 = (i & 15)*4;
            cpa16(&Vs[VBUF + r*VST + c4], &Vg[(long)(128+r)*QKVC + c4]);
        }
        asm volatile("cp.async.commit_group;\n");
    }

    asm volatile("cp.async.wait_group 1;\n");
    __syncthreads();

    // Q fragments (loop-invariant), from permuted layout
    unsigned qa[8][4];
    #pragma unroll
    for (int q = 0; q < 4; q++){
        float4 f0 = *reinterpret_cast<const float4*>(&Ps[(mrow+g  )*KJ + tg*20 + 4*q]);
        float4 f1 = *reinterpret_cast<const float4*>(&Ps[(mrow+g+8)*KJ + tg*20 + 4*q]);
        qa[2*q+0][0] = __float_as_uint(f0.x); qa[2*q+0][1] = __float_as_uint(f1.x);
        qa[2*q+0][2] = __float_as_uint(f0.y); qa[2*q+0][3] = __float_as_uint(f1.y);
        qa[2*q+1][0] = __float_as_uint(f0.z); qa[2*q+1][1] = __float_as_uint(f1.z);
        qa[2*q+1][2] = __float_as_uint(f0.w); qa[2*q+1][3] = __float_as_uint(f1.w);
    }
    __syncwarp();

    float m0 = -1e30f, m1 = -1e30f, l0 = 0.f, l1 = 0.f;
    float o[8][4];
    #pragma unroll
    for (int i = 0; i < 8; i++)
        #pragma unroll
        for (int c = 0; c < 4; c++) o[i][c] = 0.f;

    for (int j = 0; j < 16; j++){
        if (j < 15) asm volatile("cp.async.wait_group 1;\n");
        else        asm volatile("cp.async.wait_group 0;\n");
        __syncthreads();
        const float* Kb = &Ks[(j&1)*KBUF];
        const float* Vb = &Vs[(j&1)*VBUF];

        // ---- S = Q @ K^T ----
        float s[16][4];
        #pragma unroll
        for (int nf = 0; nf < 16; nf++)
            #pragma unroll
            for (int c = 0; c < 4; c++) s[nf][c] = 0.f;
        #pragma unroll
        for (int nf = 0; nf < 16; nf++){
            const float4* kr = reinterpret_cast<const float4*>(&Kb[(nf*8+g)*KJ + tg*20]);
            float4 k4[4] = {kr[0], kr[1], kr[2], kr[3]};
            #pragma unroll
            for (int q = 0; q < 4; q++){
                mma_tf32(s[nf], qa[2*q+0], __float_as_uint(k4[q].x), __float_as_uint(k4[q].y));
                mma_tf32(s[nf], qa[2*q+1], __float_as_uint(k4[q].z), __float_as_uint(k4[q].w));
            }
        }

        // ---- scale + bias ----
        const float* br0 = Bg + (long)(q0+mrow+g  )*N_ + j*128 + 2*tg;
        const float* br1 = Bg + (long)(q0+mrow+g+8)*N_ + j*128 + 2*tg;
        #pragma unroll
        for (int nf = 0; nf < 16; nf++){
            float2 t0 = *reinterpret_cast<const float2*>(br0 + nf*8);
            float2 t1 = *reinterpret_cast<const float2*>(br1 + nf*8);
            s[nf][0] = fmaf(s[nf][0], 0.125f, t0.x);
            s[nf][1] = fmaf(s[nf][1], 0.125f, t0.y);
            s[nf][2] = fmaf(s[nf][2], 0.125f, t1.x);
            s[nf][3] = fmaf(s[nf][3], 0.125f, t1.y);
        }

        // ---- online softmax ----
        float mt0 = -1e30f, mt1 = -1e30f;
        #pragma unroll
        for (int nf = 0; nf < 16; nf++){
            mt0 = fmaxf(mt0, fmaxf(s[nf][0], s[nf][1]));
            mt1 = fmaxf(mt1, fmaxf(s[nf][2], s[nf][3]));
        }
        mt0 = fmaxf(mt0, __shfl_xor_sync(0xffffffffu, mt0, 1));
        mt0 = fmaxf(mt0, __shfl_xor_sync(0xffffffffu, mt0, 2));
        mt1 = fmaxf(mt1, __shfl_xor_sync(0xffffffffu, mt1, 1));
        mt1 = fmaxf(mt1, __shfl_xor_sync(0xffffffffu, mt1, 2));
        const float mn0 = fmaxf(m0, mt0), mn1 = fmaxf(m1, mt1);
        const float cr0 = __expf(m0 - mn0), cr1 = __expf(m1 - mn1);
        m0 = mn0; m1 = mn1;

        float ls0 = 0.f, ls1 = 0.f;
        float* pr0 = &Ps[(mrow+g  )*PST + 2*tg];
        float* pr1 = &Ps[(mrow+g+8)*PST + 2*tg];
        #pragma unroll
        for (int nf = 0; nf < 16; nf++){
            float p0 = __expf(s[nf][0] - m0);
            float p1 = __expf(s[nf][1] - m0);
            float p2 = __expf(s[nf][2] - m1);
            float p3 = __expf(s[nf][3] - m1);
            ls0 += p0 + p1; ls1 += p2 + p3;
            *reinterpret_cast<float2*>(pr0 + nf*8) = make_float2(p0, p1);
            *reinterpret_cast<float2*>(pr1 + nf*8) = make_float2(p2, p3);
        }
        ls0 += __shfl_xor_sync(0xffffffffu, ls0, 1);
        ls0 += __shfl_xor_sync(0xffffffffu, ls0, 2);
        ls1 += __shfl_xor_sync(0xffffffffu, ls1, 1);
        ls1 += __shfl_xor_sync(0xffffffffu, ls1, 2);
        l0 = l0*cr0 + ls0;
        l1 = l1*cr1 + ls1;
        #pragma unroll
        for (int nf = 0; nf < 8; nf++){
            o[nf][0] *= cr0; o[nf][1] *= cr0;
            o[nf][2] *= cr1; o[nf][3] *= cr1;
        }
        __syncwarp();

        // ---- O += P @ V ----
        #pragma unroll
        for (int ks2 = 0; ks2 < 16; ks2++){
            unsigned a[4];
            a[0] = __float_as_uint(Ps[(mrow+g  )*PST + ks2*8 + tg  ]);
            a[1] = __float_as_uint(Ps[(mrow+g+8)*PST + ks2*8 + tg  ]);
            a[2] = __float_as_uint(Ps[(mrow+g  )*PST + ks2*8 + tg+4]);
            a[3] = __float_as_uint(Ps[(mrow+g+8)*PST + ks2*8 + tg+4]);
            #pragma unroll
            for (int nf = 0; nf < 8; nf++){
                unsigned b0 = __float_as_uint(Vb[(ks2*8+tg  )*VST + nf*8 + g]);
                unsigned b1 = __float_as_uint(Vb[(ks2*8+tg+4)*VST + nf*8 + g]);
                mma_tf32(o[nf], a, b0, b1);
            }
        }

        __syncthreads();
        if (j + 2 < 16){
            const int buf = j & 1;     // (j+2) & 1
            const float* kp = Kg + (long)(j+2)*128*QKVC;
            const float* vp = Vg + (long)(j+2)*128*QKVC;
            #pragma unroll
            for (int it = 0; it < 32; it++){
                int i = tid + it*256;
                int r = i >> 6, c = i & 63;
                int pj = (c&3)*20 + (c>>2);
                cpa4(&Ks[buf*KBUF + r*KJ + pj], kp + (long)r*QKVC + c);
            }
            #pragma unroll
            for (int it = 0; it < 8; it++){
                int i = tid + it*256;
                int r = i >> 4, c4 = (i & 15)*4;
                cpa16(&Vs[buf*VBUF + r*VST + c4], vp + (long)r*QKVC + c4);
            }
            asm volatile("cp.async.commit_group;\n");
        }
    }

    // ---- epilogue: O / l ----
    const float inv0 = 1.0f / l0, inv1 = 1.0f / l1;
    float* o0 = ao + (long)(bb*N_ + q0 + mrow + g  )*D_ + hh*DH_ + 2*tg;
    float* o1 = ao + (long)(bb*N_ + q0 + mrow + g+8)*D_ + hh*DH_ + 2*tg;
    #pragma unroll
    for (int nf = 0; nf < 8; nf++){
        *reinterpret_cast<float2*>(o0 + nf*8) = make_float2(o[nf][0]*inv0, o[nf][1]*inv0);
        *reinterpret_cast<float2*>(o1 + nf*8) = make_float2(o[nf][2]*inv1, o[nf][3]*inv1);
    }
}

// ---------------- TF32 tensor-core GEMM with fused epilogue ----------------
// C = act( A @ B + bias ) + residual        (row-major A,B,C)
// A staged in permuted smem: (m,k) at m*SA + (k&3)*12 + (k>>2)  -> LDS.128 frags
template<int BM,int BN,int BK,int WM,int WN,bool GELU>
__global__ void __launch_bounds__((BM/WM)*(BN/WN)*32, 2)
mma_gemm(
    const float* __restrict__ A, const float* __restrict__ Bm,
    const float* __restrict__ bias, const float* __restrict__ residual,
    float* __restrict__ C,
    int K, int lda, int ldb, int ldc)
{
    constexpr int NWN = BN/WN;
    constexpr int MF = WM/16, NF = WN/8;
    constexpr int THREADS = (BM/WM)*(BN/WN)*32;
    constexpr int SA = 48;          // 4 tg-blocks of 12 words
    constexpr int SB = BN + 8;

    extern __shared__ float smg[];
    float* As = smg;                    // [2][BM*SA]
    float* Bs = smg + 2*BM*SA;          // [2][BK*SB]

    const int bm = blockIdx.y * BM;
    const int bn = blockIdx.x * BN;
    const int tid  = threadIdx.x;
    const int wid  = tid >> 5, lane = tid & 31;
    const int wm   = wid / NWN, wn = wid % NWN;
    const int g    = lane >> 2, tg = lane & 3;

    float acc[MF][NF][4];
    #pragma unroll
    for (int i = 0; i < MF; i++)
        #pragma unroll
        for (int j = 0; j < NF; j++)
            #pragma unroll
            for (int c = 0; c < 4; c++) acc[i][j][c] = 0.f;

    constexpr int A_LD = (BM*BK)/THREADS;     // 4B copies per thread
    constexpr int B_LD = (BK*BN/4)/THREADS;   // 16B copies per thread

    auto issue = [&](int buf, int k0){
        #pragma unroll
        for (int it = 0; it < A_LD; it++){
            int i = tid + it*THREADS;
            int m = i >> 5, k = i & 31;
            cpa4(&As[buf*BM*SA + m*SA + (k&3)*12 + (k>>2)],
                 &A[(long)(bm+m)*lda + k0 + k]);
        }
        #pragma unroll
        for (int it = 0; it < B_LD; it++){
            int i = tid + it*THREADS;
            int r = i/(BN/4), c = (i%(BN/4))*4;
            cpa16(&Bs[buf*BK*SB + r*SB + c], &Bm[(long)(k0+r)*ldb + bn + c]);
        }
        asm volatile("cp.async.commit_group;\n");
    };

    const int nIter = K / BK;
    issue(0, 0);

    for (int it = 0; it < nIter; it++){
        const int buf = it & 1;
        if (it + 1 < nIter){
            issue(buf^1, (it+1)*BK);
            asm volatile("cp.async.wait_group 1;\n");
        } else {
            asm volatile("cp.async.wait_group 0;\n");
        }
        __syncthreads();
        const float* Ab = &As[buf*BM*SA];
        const float* Bb = &Bs[buf*BK*SB];

        #pragma unroll
        for (int q = 0; q < 2; q++){
            float4 ag[MF], ah[MF];
            #pragma unroll
            for (int mf = 0; mf < MF; mf++){
                const int mrow = wm*WM + mf*16;
                ag[mf] = *reinterpret_cast<const float4*>(&Ab[(mrow+g  )*SA + tg*12 + 4*q]);
                ah[mf] = *reinterpret_cast<const float4*>(&Ab[(mrow+g+8)*SA + tg*12 + 4*q]);
            }
            #pragma unroll
            for (int sh = 0; sh < 2; sh++){
                const int ks = 2*q + sh;
                unsigned bf[NF][2];
                #pragma unroll
                for (int nf = 0; nf < NF; nf++){
                    const int ncol = wn*WN + nf*8 + g;
                    bf[nf][0] = __float_as_uint(Bb[(ks*8+tg  )*SB + ncol]);
                    bf[nf][1] = __float_as_uint(Bb[(ks*8+tg+4)*SB + ncol]);
                }
                unsigned av[MF][4];
                #pragma unroll
                for (int mf = 0; mf < MF; mf++){
                    av[mf][0] = __float_as_uint(sh ? ag[mf].z : ag[mf].x);
                    av[mf][1] = __float_as_uint(sh ? ah[mf].z : ah[mf].x);
                    av[mf][2] = __float_as_uint(sh ? ag[mf].w : ag[mf].y);
                    av[mf][3] = __float_as_uint(sh ? ah[mf].w : ah[mf].y);
                }
                #pragma unroll
                for (int mf = 0; mf < MF; mf++)
                    #pragma unroll
                    for (int nf = 0; nf < NF; nf++)
                        mma_tf32(acc[mf][nf], av[mf], bf[nf][0], bf[nf][1]);
            }
        }
        __syncthreads();
    }

    #pragma unroll
    for (int mf = 0; mf < MF; mf++){
        #pragma unroll
        for (int nf = 0; nf < NF; nf++){
            const int col = bn + wn*WN + nf*8 + tg*2;
            #pragma unroll
            for (int h = 0; h < 2; h++){
                const int row = bm + wm*WM + mf*16 + g + h*8;
                float v0 = acc[mf][nf][h*2+0];
                float v1 = acc[mf][nf][h*2+1];
                if (bias){
                    v0 += bias[col];
                    v1 += bias[col + 1];
                }
                if (GELU){
                    v0 = 0.5f*v0*(1.0f + erff(v0*0.70710678118654752f));
                    v1 = 0.5f*v1*(1.0f + erff(v1*0.70710678118654752f));
                }
                if (residual){
                    v0 += residual[(long)row*ldc + col];
                    v1 += residual[(long)row*ldc + col + 1];
                }
                *reinterpret_cast<float2*>(&C[(long)row*ldc + col]) = make_float2(v0, v1);
            }
        }
    }
}

// ---------------------------------------------------------------------------
#define GEMM_SMEM ((2*128*48 + 2*32*136)*4)

extern "C" void kernel_launch(void* const* d_in, const int* in_sizes, int n_in,
                              void* d_out, int out_size)
{
    const float* x      = (const float*)d_in[0];
    const float* Wqkv   = (const float*)d_in[1];
    const float* Wout   = (const float*)d_in[2];
    const float* gamma1 = (const float*)d_in[3];
    const float* beta1  = (const float*)d_in[4];
    const float* gamma2 = (const float*)d_in[5];
    const float* beta2  = (const float*)d_in[6];
    const float* W1     = (const float*)d_in[7];
    const float* b1     = (const float*)d_in[8];
    const float* W2     = (const float*)d_in[9];
    const float* b2     = (const float*)d_in[10];
    const float* abias  = (const float*)d_in[11];
    float* out = (float*)d_out;

    float *h, *qkv, *ao, *x1, *ffn;
    cudaGetSymbolAddress((void**)&h,   g_h);
    cudaGetSymbolAddress((void**)&qkv, g_qkv);
    cudaGetSymbolAddress((void**)&ao,  g_attnout);
    cudaGetSymbolAddress((void**)&x1,  g_x1);
    cudaGetSymbolAddress((void**)&ffn, g_ffn);

    cudaFuncSetAttribute(flash_kernel, cudaFuncAttributeMaxDynamicSharedMemorySize, FA_SMEM);
    cudaFuncSetAttribute(mma_gemm<128,128,32,64,32,false>, cudaFuncAttributeMaxDynamicSharedMemorySize, GEMM_SMEM);
    cudaFuncSetAttribute(mma_gemm<128,128,32,64,32,true>,  cudaFuncAttributeMaxDynamicSharedMemorySize, GEMM_SMEM);

    // 1. h = LN(x)
    ln_kernel<<<R_, 256>>>(x, gamma1, beta1, h);

    // 2. qkv = h @ Wqkv
    mma_gemm<128,128,32,64,32,false><<<dim3(QKVC/128, R_/128), 256, GEMM_SMEM>>>(
        h, Wqkv, nullptr, nullptr, qkv, D_, D_, QKVC, QKVC);

    // 3-5. fused flash attention -> ao
    flash_kernel<<<dim3(N_/128, H_, B_), 256, FA_SMEM>>>(qkv, abias, ao);

    // 6. x1 = ao @ Wout + x
    mma_gemm<128,128,32,64,32,false><<<dim3(D_/128, R_/128), 256, GEMM_SMEM>>>(
        ao, Wout, nullptr, x, x1, D_, D_, D_, D_);

    // 7. h = LN(x1)
    ln_kernel<<<R_, 256>>>(x1, gamma2, beta2, h);

    // 8. ffn = gelu(h @ W1 + b1)
    mma_gemm<128,128,32,64,32,true><<<dim3(M_/128, R_/128), 256, GEMM_SMEM>>>(
        h, W1, b1, nullptr, ffn, D_, D_, M_, M_);

    // 9. out = ffn @ W2 + b2 + x1
    mma_gemm<128,128,32,64,32,false><<<dim3(D_/128, R_/128), 256, GEMM_SMEM>>>(
        ffn, W2, b2, x1, out, M_, M_, D_, D_);
}

// round 5
// speedup vs baseline: 1.2319x; 1.2319x over previous
#include <cuda_runtime.h>
#include <math.h>

// Problem dims (fixed instance)
#define B_   2
#define N_   2048
#define D_   768
#define H_   12
#define DH_  64
#define M_   3072
#define R_   (B_*N_)          // 4096 token rows
#define QKVC (3*H_*DH_)       // 2304

// ---------------- scratch (device globals; no allocations allowed) ---------
__device__ float g_h[(size_t)R_*D_];
__device__ float g_qkv[(size_t)R_*QKVC];
__device__ float g_attnout[(size_t)R_*D_];
__device__ float g_x1[(size_t)R_*D_];
__device__ float g_ffn[(size_t)R_*M_];

// ---------------- helpers ---------------------------------------------------
__device__ __forceinline__ void cpa16(void* dst, const void* src){
    unsigned d = (unsigned)__cvta_generic_to_shared(dst);
    asm volatile("cp.async.cg.shared.global [%0], [%1], 16;\n" :: "r"(d), "l"(src));
}
// raw fp32 bits into tf32 mma (HW uses upper 19 bits; RZ truncation)
__device__ __forceinline__ void mma_tf32(float* c, const unsigned* a, unsigned b0, unsigned b1){
    asm volatile("mma.sync.aligned.m16n8k8.row.col.f32.tf32.tf32.f32 "
        "{%0,%1,%2,%3}, {%4,%5,%6,%7}, {%8,%9}, {%0,%1,%2,%3};\n"
        : "+f"(c[0]),"+f"(c[1]),"+f"(c[2]),"+f"(c[3])
        : "r"(a[0]),"r"(a[1]),"r"(a[2]),"r"(a[3]), "r"(b0),"r"(b1));
}
__device__ __forceinline__ unsigned fbits(float f){ return __float_as_uint(f); }

// ---------------- LayerNorm: one block (256 thr) per row of 768 ------------
__global__ void ln_kernel(const float* __restrict__ x,
                          const float* __restrict__ gamma,
                          const float* __restrict__ beta,
                          float* __restrict__ out)
{
    const int row = blockIdx.x;
    const float* xr = x + (long)row * D_;
    float v[3];
    float s = 0.f, s2 = 0.f;
    #pragma unroll
    for (int i = 0; i < 3; i++) {
        v[i] = xr[threadIdx.x + i*256];
        s  += v[i];
        s2 += v[i]*v[i];
    }
    #pragma unroll
    for (int o = 16; o > 0; o >>= 1) {
        s  += __shfl_xor_sync(0xffffffffu, s,  o);
        s2 += __shfl_xor_sync(0xffffffffu, s2, o);
    }
    __shared__ float sa[8], sb[8];
    int w = threadIdx.x >> 5, l = threadIdx.x & 31;
    if (l == 0) { sa[w] = s; sb[w] = s2; }
    __syncthreads();
    s = 0.f; s2 = 0.f;
    #pragma unroll
    for (int i = 0; i < 8; i++) { s += sa[i]; s2 += sb[i]; }

    const float mean = s * (1.0f / D_);
    const float var  = s2 * (1.0f / D_) - mean*mean;
    const float rstd = rsqrtf(var + 1e-5f);
    float* o = out + (long)row * D_;
    #pragma unroll
    for (int i = 0; i < 3; i++) {
        int c = threadIdx.x + i*256;
        o[c] = (v[i] - mean) * rstd * gamma[c] + beta[c];
    }
}

// ---------------- Flash attention -------------------------------------------
// softmax(QK^T*scale + bias) @ V, fused.  128 q-rows per block, 8 warps.
// (softmax(d)*softmax(bias) renormalized == softmax(d + bias))
#define KST 68
#define VST 72
#define PST 132
#define KS_OFF 0
#define VS_OFF (2*128*KST)
#define PS_OFF (2*128*KST + 2*128*VST)
#define FA_SMEM ((2*128*KST + 2*128*VST + 128*PST)*4)

__global__ void __launch_bounds__(256,1)
flash_kernel(const float* __restrict__ qkv,
             const float* __restrict__ bias,
             float* __restrict__ ao)
{
    extern __shared__ float sm[];
    float* Ks = sm + KS_OFF;
    float* Vs = sm + VS_OFF;
    float* Ps = sm + PS_OFF;

    const int qt = blockIdx.x;       // 0..15
    const int hh = blockIdx.y;       // 0..11
    const int bb = blockIdx.z;       // 0..1
    const int q0 = qt*128;
    const long base = (long)bb*N_*QKVC;
    const float* Qg = qkv + base + hh*DH_;
    const float* Kg = qkv + base + H_*DH_ + hh*DH_;
    const float* Vg = qkv + base + 2*H_*DH_ + hh*DH_;
    const float* Bg = bias + (long)hh*N_*N_;

    const int tid = threadIdx.x, wid = tid>>5, lane = tid&31;
    const int g = lane>>2, tg = lane&3;
    const int mrow = wid*16;

    // prologue loads: group0 = {Q, K0, V0}, group1 = {K1, V1}
    {
        #pragma unroll
        for (int it = 0; it < 8; it++){
            int i = tid + it*256;
            int r = i >> 4, c4 = (i & 15)*4;
            cpa16(&Ps[r*KST + c4], &Qg[(long)(q0+r)*QKVC + c4]);
            cpa16(&Ks[r*KST + c4], &Kg[(long)r*QKVC + c4]);
            cpa16(&Vs[r*VST + c4], &Vg[(long)r*QKVC + c4]);
        }
        asm volatile("cp.async.commit_group;\n");
        #pragma unroll
        for (int it = 0; it < 8; it++){
            int i = tid + it*256;
            int r = i >> 4, c4 = (i & 15)*4;
            cpa16(&Ks[128*KST + r*KST + c4], &Kg[(long)(128+r)*QKVC + c4]);
            cpa16(&Vs[128*VST + r*VST + c4], &Vg[(long)(128+r)*QKVC + c4]);
        }
        asm volatile("cp.async.commit_group;\n");
    }

    asm volatile("cp.async.wait_group 1;\n");
    __syncthreads();

    // Q fragments (loop-invariant), raw bits
    unsigned qf[8][4];
    #pragma unroll
    for (int ks = 0; ks < 8; ks++){
        qf[ks][0] = fbits(Ps[(mrow+g  )*KST + ks*8 + tg  ]);
        qf[ks][1] = fbits(Ps[(mrow+g+8)*KST + ks*8 + tg  ]);
        qf[ks][2] = fbits(Ps[(mrow+g  )*KST + ks*8 + tg+4]);
        qf[ks][3] = fbits(Ps[(mrow+g+8)*KST + ks*8 + tg+4]);
    }
    __syncwarp();

    float m0 = -1e30f, m1 = -1e30f, l0 = 0.f, l1 = 0.f;
    float o[8][4];
    #pragma unroll
    for (int i = 0; i < 8; i++)
        #pragma unroll
        for (int c = 0; c < 4; c++) o[i][c] = 0.f;

    for (int j = 0; j < 16; j++){
        if (j < 15) asm volatile("cp.async.wait_group 1;\n");
        else        asm volatile("cp.async.wait_group 0;\n");
        __syncthreads();
        const float* Kb = &Ks[(j&1)*128*KST];
        const float* Vb = &Vs[(j&1)*128*VST];

        // ---- S = Q @ K^T ----
        float s[16][4];
        #pragma unroll
        for (int nf = 0; nf < 16; nf++)
            #pragma unroll
            for (int c = 0; c < 4; c++) s[nf][c] = 0.f;
        #pragma unroll
        for (int nf = 0; nf < 16; nf++){
            #pragma unroll
            for (int ks = 0; ks < 8; ks++){
                unsigned b0 = fbits(Kb[(nf*8+g)*KST + ks*8 + tg  ]);
                unsigned b1 = fbits(Kb[(nf*8+g)*KST + ks*8 + tg+4]);
                mma_tf32(s[nf], qf[ks], b0, b1);
            }
        }

        // ---- scale + bias ----
        const float* br0 = Bg + (long)(q0+mrow+g  )*N_ + j*128 + 2*tg;
        const float* br1 = Bg + (long)(q0+mrow+g+8)*N_ + j*128 + 2*tg;
        #pragma unroll
        for (int nf = 0; nf < 16; nf++){
            float2 t0 = *reinterpret_cast<const float2*>(br0 + nf*8);
            float2 t1 = *reinterpret_cast<const float2*>(br1 + nf*8);
            s[nf][0] = fmaf(s[nf][0], 0.125f, t0.x);
            s[nf][1] = fmaf(s[nf][1], 0.125f, t0.y);
            s[nf][2] = fmaf(s[nf][2], 0.125f, t1.x);
            s[nf][3] = fmaf(s[nf][3], 0.125f, t1.y);
        }

        // ---- online softmax ----
        float mt0 = -1e30f, mt1 = -1e30f;
        #pragma unroll
        for (int nf = 0; nf < 16; nf++){
            mt0 = fmaxf(mt0, fmaxf(s[nf][0], s[nf][1]));
            mt1 = fmaxf(mt1, fmaxf(s[nf][2], s[nf][3]));
        }
        mt0 = fmaxf(mt0, __shfl_xor_sync(0xffffffffu, mt0, 1));
        mt0 = fmaxf(mt0, __shfl_xor_sync(0xffffffffu, mt0, 2));
        mt1 = fmaxf(mt1, __shfl_xor_sync(0xffffffffu, mt1, 1));
        mt1 = fmaxf(mt1, __shfl_xor_sync(0xffffffffu, mt1, 2));
        const float mn0 = fmaxf(m0, mt0), mn1 = fmaxf(m1, mt1);
        const float cr0 = __expf(m0 - mn0), cr1 = __expf(m1 - mn1);
        m0 = mn0; m1 = mn1;

        float ls0 = 0.f, ls1 = 0.f;
        float* pr0 = &Ps[(mrow+g  )*PST + 2*tg];
        float* pr1 = &Ps[(mrow+g+8)*PST + 2*tg];
        #pragma unroll
        for (int nf = 0; nf < 16; nf++){
            float p0 = __expf(s[nf][0] - m0);
            float p1 = __expf(s[nf][1] - m0);
            float p2 = __expf(s[nf][2] - m1);
            float p3 = __expf(s[nf][3] - m1);
            ls0 += p0 + p1; ls1 += p2 + p3;
            *reinterpret_cast<float2*>(pr0 + nf*8) = make_float2(p0, p1);
            *reinterpret_cast<float2*>(pr1 + nf*8) = make_float2(p2, p3);
        }
        ls0 += __shfl_xor_sync(0xffffffffu, ls0, 1);
        ls0 += __shfl_xor_sync(0xffffffffu, ls0, 2);
        ls1 += __shfl_xor_sync(0xffffffffu, ls1, 1);
        ls1 += __shfl_xor_sync(0xffffffffu, ls1, 2);
        l0 = l0*cr0 + ls0;
        l1 = l1*cr1 + ls1;
        #pragma unroll
        for (int nf = 0; nf < 8; nf++){
            o[nf][0] *= cr0; o[nf][1] *= cr0;
            o[nf][2] *= cr1; o[nf][3] *= cr1;
        }
        __syncwarp();

        // ---- O += P @ V ----
        #pragma unroll
        for (int ks2 = 0; ks2 < 16; ks2++){
            unsigned a[4];
            a[0] = fbits(Ps[(mrow+g  )*PST + ks2*8 + tg  ]);
            a[1] = fbits(Ps[(mrow+g+8)*PST + ks2*8 + tg  ]);
            a[2] = fbits(Ps[(mrow+g  )*PST + ks2*8 + tg+4]);
            a[3] = fbits(Ps[(mrow+g+8)*PST + ks2*8 + tg+4]);
            #pragma unroll
            for (int nf = 0; nf < 8; nf++){
                unsigned b0 = fbits(Vb[(ks2*8+tg  )*VST + nf*8 + g]);
                unsigned b1 = fbits(Vb[(ks2*8+tg+4)*VST + nf*8 + g]);
                mma_tf32(o[nf], a, b0, b1);
            }
        }

        __syncthreads();
        if (j + 2 < 16){
            const int buf = j & 1;     // (j+2) & 1
            const float* kp = Kg + (long)(j+2)*128*QKVC;
            const float* vp = Vg + (long)(j+2)*128*QKVC;
            #pragma unroll
            for (int it = 0; it < 8; it++){
                int i = tid + it*256;
                int r = i >> 4, c4 = (i & 15)*4;
                cpa16(&Ks[buf*128*KST + r*KST + c4], kp + (long)r*QKVC + c4);
                cpa16(&Vs[buf*128*VST + r*VST + c4], vp + (long)r*QKVC + c4);
            }
            asm volatile("cp.async.commit_group;\n");
        }
    }

    // ---- epilogue: O / l ----
    const float inv0 = 1.0f / l0, inv1 = 1.0f / l1;
    float* o0 = ao + (long)(bb*N_ + q0 + mrow + g  )*D_ + hh*DH_ + 2*tg;
    float* o1 = ao + (long)(bb*N_ + q0 + mrow + g+8)*D_ + hh*DH_ + 2*tg;
    #pragma unroll
    for (int nf = 0; nf < 8; nf++){
        *reinterpret_cast<float2*>(o0 + nf*8) = make_float2(o[nf][0]*inv0, o[nf][1]*inv0);
        *reinterpret_cast<float2*>(o1 + nf*8) = make_float2(o[nf][2]*inv1, o[nf][3]*inv1);
    }
}

// ---------------- TF32 tensor-core GEMM with fused epilogue ----------------
// C = act( A @ B + bias ) + residual        (row-major A,B,C)
template<int BM,int BN,int BK,int WM,int WN,bool GELU>
__global__ void __launch_bounds__((BM/WM)*(BN/WN)*32, 2)
mma_gemm(
    const float* __restrict__ A, const float* __restrict__ Bm,
    const float* __restrict__ bias, const float* __restrict__ residual,
    float* __restrict__ C,
    int K, int lda, int ldb, int ldc)
{
    constexpr int NWN = BN/WN;
    constexpr int MF = WM/16, NF = WN/8;
    constexpr int THREADS = (BM/WM)*(BN/WN)*32;
    constexpr int SA = BK + 4;
    constexpr int SB = BN + 8;

    extern __shared__ float smg[];
    float* As = smg;                    // [2][BM*SA]
    float* Bs = smg + 2*BM*SA;          // [2][BK*SB]

    const int bm = blockIdx.y * BM;
    const int bn = blockIdx.x * BN;
    const int tid  = threadIdx.x;
    const int wid  = tid >> 5, lane = tid & 31;
    const int wm   = wid / NWN, wn = wid % NWN;
    const int g    = lane >> 2, tg = lane & 3;

    float acc[MF][NF][4];
    #pragma unroll
    for (int i = 0; i < MF; i++)
        #pragma unroll
        for (int j = 0; j < NF; j++)
            #pragma unroll
            for (int c = 0; c < 4; c++) acc[i][j][c] = 0.f;

    constexpr int A_LD = (BM*BK/4)/THREADS;
    constexpr int B_LD = (BK*BN/4)/THREADS;

    auto issue = [&](int buf, int k0){
        #pragma unroll
        for (int it = 0; it < A_LD; it++){
            int i = tid + it*THREADS;
            int r = i/(BK/4), c = (i%(BK/4))*4;
            cpa16(&As[buf*BM*SA + r*SA + c], &A[(long)(bm+r)*lda + k0 + c]);
        }
        #pragma unroll
        for (int it = 0; it < B_LD; it++){
            int i = tid + it*THREADS;
            int r = i/(BN/4), c = (i%(BN/4))*4;
            cpa16(&Bs[buf*BK*SB + r*SB + c], &Bm[(long)(k0+r)*ldb + bn + c]);
        }
        asm volatile("cp.async.commit_group;\n");
    };

    const int nIter = K / BK;
    issue(0, 0);

    for (int it = 0; it < nIter; it++){
        const int buf = it & 1;
        if (it + 1 < nIter){
            issue(buf^1, (it+1)*BK);
            asm volatile("cp.async.wait_group 1;\n");
        } else {
            asm volatile("cp.async.wait_group 0;\n");
        }
        __syncthreads();
        const float* Ab = &As[buf*BM*SA];
        const float* Bb = &Bs[buf*BK*SB];

        #pragma unroll
        for (int ks = 0; ks < BK/8; ks++){
            unsigned a[MF][4], b[NF][2];
            #pragma unroll
            for (int mf = 0; mf < MF; mf++){
                const int mrow = wm*WM + mf*16;
                a[mf][0] = fbits(Ab[(mrow+g  )*SA + ks*8 + tg  ]);
                a[mf][1] = fbits(Ab[(mrow+g+8)*SA + ks*8 + tg  ]);
                a[mf][2] = fbits(Ab[(mrow+g  )*SA + ks*8 + tg+4]);
                a[mf][3] = fbits(Ab[(mrow+g+8)*SA + ks*8 + tg+4]);
            }
            #pragma unroll
            for (int nf = 0; nf < NF; nf++){
                const int ncol = wn*WN + nf*8 + g;
                b[nf][0] = fbits(Bb[(ks*8+tg  )*SB + ncol]);
                b[nf][1] = fbits(Bb[(ks*8+tg+4)*SB + ncol]);
            }
            #pragma unroll
            for (int mf = 0; mf < MF; mf++)
                #pragma unroll
                for (int nf = 0; nf < NF; nf++)
                    mma_tf32(acc[mf][nf], a[mf], b[nf][0], b[nf][1]);
        }
        __syncthreads();
    }

    #pragma unroll
    for (int mf = 0; mf < MF; mf++){
        #pragma unroll
        for (int nf = 0; nf < NF; nf++){
            const int col = bn + wn*WN + nf*8 + tg*2;
            #pragma unroll
            for (int h = 0; h < 2; h++){
                const int row = bm + wm*WM + mf*16 + g + h*8;
                float v0 = acc[mf][nf][h*2+0];
                float v1 = acc[mf][nf][h*2+1];
                if (bias){
                    v0 += bias[col];
                    v1 += bias[col + 1];
                }
                if (GELU){
                    v0 = 0.5f*v0*(1.0f + erff(v0*0.70710678118654752f));
                    v1 = 0.5f*v1*(1.0f + erff(v1*0.70710678118654752f));
                }
                if (residual){
                    v0 += residual[(long)row*ldc + col];
                    v1 += residual[(long)row*ldc + col + 1];
                }
                *reinterpret_cast<float2*>(&C[(long)row*ldc + col]) = make_float2(v0, v1);
            }
        }
    }
}

// ---------------------------------------------------------------------------
#define GEMM_SMEM ((2*128*36 + 2*32*136)*4)

extern "C" void kernel_launch(void* const* d_in, const int* in_sizes, int n_in,
                              void* d_out, int out_size)
{
    const float* x      = (const float*)d_in[0];
    const float* Wqkv   = (const float*)d_in[1];
    const float* Wout   = (const float*)d_in[2];
    const float* gamma1 = (const float*)d_in[3];
    const float* beta1  = (const float*)d_in[4];
    const float* gamma2 = (const float*)d_in[5];
    const float* beta2  = (const float*)d_in[6];
    const float* W1     = (const float*)d_in[7];
    const float* b1     = (const float*)d_in[8];
    const float* W2     = (const float*)d_in[9];
    const float* b2     = (const float*)d_in[10];
    const float* abias  = (const float*)d_in[11];
    float* out = (float*)d_out;

    float *h, *qkv, *ao, *x1, *ffn;
    cudaGetSymbolAddress((void**)&h,   g_h);
    cudaGetSymbolAddress((void**)&qkv, g_qkv);
    cudaGetSymbolAddress((void**)&ao,  g_attnout);
    cudaGetSymbolAddress((void**)&x1,  g_x1);
    cudaGetSymbolAddress((void**)&ffn, g_ffn);

    cudaFuncSetAttribute(flash_kernel, cudaFuncAttributeMaxDynamicSharedMemorySize, FA_SMEM);
    cudaFuncSetAttribute(mma_gemm<128,128,32,64,32,false>, cudaFuncAttributeMaxDynamicSharedMemorySize, GEMM_SMEM);
    cudaFuncSetAttribute(mma_gemm<128,128,32,64,32,true>,  cudaFuncAttributeMaxDynamicSharedMemorySize, GEMM_SMEM);

    // 1. h = LN(x)
    ln_kernel<<<R_, 256>>>(x, gamma1, beta1, h);

    // 2. qkv = h @ Wqkv
    mma_gemm<128,128,32,64,32,false><<<dim3(QKVC/128, R_/128), 256, GEMM_SMEM>>>(
        h, Wqkv, nullptr, nullptr, qkv, D_, D_, QKVC, QKVC);

    // 3-5. fused flash attention -> ao
    flash_kernel<<<dim3(N_/128, H_, B_), 256, FA_SMEM>>>(qkv, abias, ao);

    // 6. x1 = ao @ Wout + x
    mma_gemm<128,128,32,64,32,false><<<dim3(D_/128, R_/128), 256, GEMM_SMEM>>>(
        ao, Wout, nullptr, x, x1, D_, D_, D_, D_);

    // 7. h = LN(x1)
    ln_kernel<<<R_, 256>>>(x1, gamma2, beta2, h);

    // 8. ffn = gelu(h @ W1 + b1)
    mma_gemm<128,128,32,64,32,true><<<dim3(M_/128, R_/128), 256, GEMM_SMEM>>>(
        h, W1, b1, nullptr, ffn, D_, D_, M_, M_);

    // 9. out = ffn @ W2 + b2 + x1
    mma_gemm<128,128,32,64,32,false><<<dim3(D_/128, R_/128), 256, GEMM_SMEM>>>(
        ffn, W2, b2, x1, out, M_, M_, D_, D_);
}

// round 6
// speedup vs baseline: 1.8678x; 1.5162x over previous
#include <cuda_runtime.h>
#include <cuda_fp16.h>
#include <math.h>

#define B_   2
#define N_   2048
#define D_   768
#define H_   12
#define DH_  64
#define M_   3072
#define R_   (B_*N_)
#define QKVC (3*H_*DH_)

// ---------------- scratch (device globals) ----------------------------------
__device__ __half g_h[(size_t)R_*D_];
__device__ __half g_qkv[(size_t)R_*QKVC];
__device__ __half g_vt[(size_t)B_*H_*DH_*N_];
__device__ __half g_ao[(size_t)R_*D_];
__device__ float  g_x1[(size_t)R_*D_];
__device__ __half g_ffn[(size_t)R_*M_];
__device__ __half g_wqkvT[(size_t)QKVC*D_];
__device__ __half g_woutT[(size_t)D_*D_];
__device__ __half g_w1T[(size_t)M_*D_];
__device__ __half g_w2T[(size_t)D_*M_];

// ---------------- helpers ----------------------------------------------------
__device__ __forceinline__ void cpa16(void* dst, const void* src){
    unsigned d = (unsigned)__cvta_generic_to_shared(dst);
    asm volatile("cp.async.cg.shared.global [%0], [%1], 16;\n" :: "r"(d), "l"(src));
}
__device__ __forceinline__ void mma_f16(float* c, const unsigned* a, unsigned b0, unsigned b1){
    asm volatile("mma.sync.aligned.m16n8k16.row.col.f32.f16.f16.f32 "
        "{%0,%1,%2,%3}, {%4,%5,%6,%7}, {%8,%9}, {%0,%1,%2,%3};\n"
        : "+f"(c[0]),"+f"(c[1]),"+f"(c[2]),"+f"(c[3])
        : "r"(a[0]),"r"(a[1]),"r"(a[2]),"r"(a[3]), "r"(b0),"r"(b1));
}
__device__ __forceinline__ unsigned ldh2(const __half* p){ return *reinterpret_cast<const unsigned*>(p); }
__device__ __forceinline__ unsigned pk2(float a, float b){
    __half2 h = __floats2half2_rn(a, b);
    return *reinterpret_cast<unsigned*>(&h);
}

// ---------------- weight convert+transpose: [K][N] fp32 -> [N][K] fp16 ------
__global__ void convT(const float* __restrict__ in, __half* __restrict__ out, int K, int N)
{
    __shared__ float t[32][33];
    const int n0 = blockIdx.x*32, k0 = blockIdx.y*32;
    #pragma unroll
    for (int i = 0; i < 4; i++)
        t[threadIdx.y + i*8][threadIdx.x] =
            in[(long)(k0 + threadIdx.y + i*8)*N + n0 + threadIdx.x];
    __syncthreads();
    #pragma unroll
    for (int i = 0; i < 4; i++)
        out[(long)(n0 + threadIdx.y + i*8)*K + k0 + threadIdx.x] =
            __float2half_rn(t[threadIdx.x][threadIdx.y + i*8]);
}

// ---------------- V transpose: qkv fp16 -> vt[b][h][dh][token] ---------------
__global__ void vtrans(const __half* __restrict__ qkv, __half* __restrict__ vt)
{
    __shared__ __half t[32][34];
    const int n0 = blockIdx.x*32;
    const int yy = blockIdx.y;
    const int d0 = (yy & 1)*32;
    const int hh = (yy >> 1) % H_;
    const int bb = yy / (2*H_);
    #pragma unroll
    for (int i = 0; i < 4; i++)
        t[threadIdx.y + i*8][threadIdx.x] =
            qkv[(long)(bb*N_ + n0 + threadIdx.y + i*8)*QKVC + 2*H_*DH_ + hh*DH_ + d0 + threadIdx.x];
    __syncthreads();
    #pragma unroll
    for (int i = 0; i < 4; i++)
        vt[(long)((bb*H_ + hh)*DH_ + d0 + threadIdx.y + i*8)*N_ + n0 + threadIdx.x] =
            t[threadIdx.x][threadIdx.y + i*8];
}

// ---------------- LayerNorm: fp32 in -> fp16 out -----------------------------
__global__ void ln_kernel(const float* __restrict__ x,
                          const float* __restrict__ gamma,
                          const float* __restrict__ beta,
                          __half* __restrict__ out)
{
    const int row = blockIdx.x;
    const float* xr = x + (long)row * D_;
    float v[3];
    float s = 0.f, s2 = 0.f;
    #pragma unroll
    for (int i = 0; i < 3; i++) {
        v[i] = xr[threadIdx.x + i*256];
        s  += v[i];
        s2 += v[i]*v[i];
    }
    #pragma unroll
    for (int o = 16; o > 0; o >>= 1) {
        s  += __shfl_xor_sync(0xffffffffu, s,  o);
        s2 += __shfl_xor_sync(0xffffffffu, s2, o);
    }
    __shared__ float sa[8], sb[8];
    int w = threadIdx.x >> 5, l = threadIdx.x & 31;
    if (l == 0) { sa[w] = s; sb[w] = s2; }
    __syncthreads();
    s = 0.f; s2 = 0.f;
    #pragma unroll
    for (int i = 0; i < 8; i++) { s += sa[i]; s2 += sb[i]; }

    const float mean = s * (1.0f / D_);
    const float var  = s2 * (1.0f / D_) - mean*mean;
    const float rstd = rsqrtf(var + 1e-5f);
    __half* o = out + (long)row * D_;
    #pragma unroll
    for (int i = 0; i < 3; i++) {
        int c = threadIdx.x + i*256;
        o[c] = __float2half_rn((v[i] - mean) * rstd * gamma[c] + beta[c]);
    }
}

// ---------------- Flash attention (fp16 tensor path) -------------------------
// softmax(QK^T*scale + bias) @ V.  128 q-rows/block, 8 warps, K-tile 128.
#define KSTH 72            // K/Q smem row stride (halves)
#define VSTH 136           // V smem row stride (halves): [dh][token]
#define PSTH 136           // P smem row stride (halves)
#define KBUFH (128*KSTH)
#define VBUFH (64*VSTH)
#define VS_OFFH (2*KBUFH)
#define PS_OFFH (2*KBUFH + 2*VBUFH)
#define FA_SMEM ((2*KBUFH + 2*VBUFH + 128*PSTH)*2)

__global__ void __launch_bounds__(256,1)
flash_kernel(const __half* __restrict__ qkv,
             const __half* __restrict__ vt,
             const float* __restrict__ bias,
             __half* __restrict__ ao)
{
    extern __shared__ __half smh[];
    __half* Ks = smh;
    __half* Vs = smh + VS_OFFH;
    __half* Ps = smh + PS_OFFH;

    const int qt = blockIdx.x, hh = blockIdx.y, bb = blockIdx.z;
    const int q0 = qt*128;
    const long base = (long)bb*N_*QKVC;
    const __half* Qg = qkv + base + hh*DH_;
    const __half* Kg = qkv + base + H_*DH_ + hh*DH_;
    const __half* Vt = vt + (long)(bb*H_ + hh)*DH_*N_;
    const float* Bg = bias + (long)hh*N_*N_;

    const int tid = threadIdx.x, wid = tid>>5, lane = tid&31;
    const int g = lane>>2, tg = lane&3;
    const int mrow = wid*16;

    // prologue: group0 = {Q, K0, V0}, group1 = {K1, V1}
    {
        #pragma unroll
        for (int it = 0; it < 4; it++){
            int i = tid + it*256;
            int r = i >> 3, c8 = (i & 7)*8;
            cpa16(&Ps[r*KSTH + c8], &Qg[(long)(q0+r)*QKVC + c8]);
            cpa16(&Ks[r*KSTH + c8], &Kg[(long)r*QKVC + c8]);
        }
        #pragma unroll
        for (int it = 0; it < 4; it++){
            int i = tid + it*256;
            int r = i >> 4, c8 = (i & 15)*8;
            cpa16(&Vs[r*VSTH + c8], &Vt[(long)r*N_ + c8]);
        }
        asm volatile("cp.async.commit_group;\n");
        #pragma unroll
        for (int it = 0; it < 4; it++){
            int i = tid + it*256;
            int r = i >> 3, c8 = (i & 7)*8;
            cpa16(&Ks[KBUFH + r*KSTH + c8], &Kg[(long)(128+r)*QKVC + c8]);
        }
        #pragma unroll
        for (int it = 0; it < 4; it++){
            int i = tid + it*256;
            int r = i >> 4, c8 = (i & 15)*8;
            cpa16(&Vs[VBUFH + r*VSTH + c8], &Vt[(long)r*N_ + 128 + c8]);
        }
        asm volatile("cp.async.commit_group;\n");
    }

    asm volatile("cp.async.wait_group 1;\n");
    __syncthreads();

    // Q fragments (loop-invariant): 4 k-steps of 16
    unsigned qf[4][4];
    #pragma unroll
    for (int ks = 0; ks < 4; ks++){
        qf[ks][0] = ldh2(&Ps[(mrow+g  )*KSTH + ks*16 + 2*tg]);
        qf[ks][1] = ldh2(&Ps[(mrow+g+8)*KSTH + ks*16 + 2*tg]);
        qf[ks][2] = ldh2(&Ps[(mrow+g  )*KSTH + ks*16 + 2*tg + 8]);
        qf[ks][3] = ldh2(&Ps[(mrow+g+8)*KSTH + ks*16 + 2*tg + 8]);
    }
    __syncwarp();

    float m0 = -1e30f, m1 = -1e30f, l0 = 0.f, l1 = 0.f;
    float o[8][4];
    #pragma unroll
    for (int i = 0; i < 8; i++)
        #pragma unroll
        for (int c = 0; c < 4; c++) o[i][c] = 0.f;

    for (int j = 0; j < 16; j++){
        if (j < 15) asm volatile("cp.async.wait_group 1;\n");
        else        asm volatile("cp.async.wait_group 0;\n");
        __syncthreads();
        const __half* Kb = &Ks[(j&1)*KBUFH];
        const __half* Vb = &Vs[(j&1)*VBUFH];

        // ---- S = Q @ K^T ----
        float s[16][4];
        #pragma unroll
        for (int nf = 0; nf < 16; nf++)
            #pragma unroll
            for (int c = 0; c < 4; c++) s[nf][c] = 0.f;
        #pragma unroll
        for (int nf = 0; nf < 16; nf++){
            #pragma unroll
            for (int ks = 0; ks < 4; ks++){
                unsigned b0 = ldh2(&Kb[(nf*8+g)*KSTH + ks*16 + 2*tg]);
                unsigned b1 = ldh2(&Kb[(nf*8+g)*KSTH + ks*16 + 2*tg + 8]);
                mma_f16(s[nf], qf[ks], b0, b1);
            }
        }

        // ---- scale + bias ----
        const float* br0 = Bg + (long)(q0+mrow+g  )*N_ + j*128 + 2*tg;
        const float* br1 = Bg + (long)(q0+mrow+g+8)*N_ + j*128 + 2*tg;
        #pragma unroll
        for (int nf = 0; nf < 16; nf++){
            float2 t0 = *reinterpret_cast<const float2*>(br0 + nf*8);
            float2 t1 = *reinterpret_cast<const float2*>(br1 + nf*8);
            s[nf][0] = fmaf(s[nf][0], 0.125f, t0.x);
            s[nf][1] = fmaf(s[nf][1], 0.125f, t0.y);
            s[nf][2] = fmaf(s[nf][2], 0.125f, t1.x);
            s[nf][3] = fmaf(s[nf][3], 0.125f, t1.y);
        }

        // ---- online softmax ----
        float mt0 = -1e30f, mt1 = -1e30f;
        #pragma unroll
        for (int nf = 0; nf < 16; nf++){
            mt0 = fmaxf(mt0, fmaxf(s[nf][0], s[nf][1]));
            mt1 = fmaxf(mt1, fmaxf(s[nf][2], s[nf][3]));
        }
        mt0 = fmaxf(mt0, __shfl_xor_sync(0xffffffffu, mt0, 1));
        mt0 = fmaxf(mt0, __shfl_xor_sync(0xffffffffu, mt0, 2));
        mt1 = fmaxf(mt1, __shfl_xor_sync(0xffffffffu, mt1, 1));
        mt1 = fmaxf(mt1, __shfl_xor_sync(0xffffffffu, mt1, 2));
        const float mn0 = fmaxf(m0, mt0), mn1 = fmaxf(m1, mt1);
        const float cr0 = __expf(m0 - mn0), cr1 = __expf(m1 - mn1);
        m0 = mn0; m1 = mn1;

        float ls0 = 0.f, ls1 = 0.f;
        __half* pr0 = &Ps[(mrow+g  )*PSTH + 2*tg];
        __half* pr1 = &Ps[(mrow+g+8)*PSTH + 2*tg];
        #pragma unroll
        for (int nf = 0; nf < 16; nf++){
            float p0 = __expf(s[nf][0] - m0);
            float p1 = __expf(s[nf][1] - m0);
            float p2 = __expf(s[nf][2] - m1);
            float p3 = __expf(s[nf][3] - m1);
            ls0 += p0 + p1; ls1 += p2 + p3;
            *reinterpret_cast<unsigned*>(pr0 + nf*8) = pk2(p0, p1);
            *reinterpret_cast<unsigned*>(pr1 + nf*8) = pk2(p2, p3);
        }
        ls0 += __shfl_xor_sync(0xffffffffu, ls0, 1);
        ls0 += __shfl_xor_sync(0xffffffffu, ls0, 2);
        ls1 += __shfl_xor_sync(0xffffffffu, ls1, 1);
        ls1 += __shfl_xor_sync(0xffffffffu, ls1, 2);
        l0 = l0*cr0 + ls0;
        l1 = l1*cr1 + ls1;
        #pragma unroll
        for (int nf = 0; nf < 8; nf++){
            o[nf][0] *= cr0; o[nf][1] *= cr0;
            o[nf][2] *= cr1; o[nf][3] *= cr1;
        }
        __syncwarp();

        // ---- O += P @ V ----   (V in [dh][token] layout)
        #pragma unroll
        for (int ks2 = 0; ks2 < 8; ks2++){
            unsigned a[4];
            a[0] = ldh2(&Ps[(mrow+g  )*PSTH + ks2*16 + 2*tg]);
            a[1] = ldh2(&Ps[(mrow+g+8)*PSTH + ks2*16 + 2*tg]);
            a[2] = ldh2(&Ps[(mrow+g  )*PSTH + ks2*16 + 2*tg + 8]);
            a[3] = ldh2(&Ps[(mrow+g+8)*PSTH + ks2*16 + 2*tg + 8]);
            #pragma unroll
            for (int nf = 0; nf < 8; nf++){
                unsigned b0 = ldh2(&Vb[(nf*8+g)*VSTH + ks2*16 + 2*tg]);
                unsigned b1 = ldh2(&Vb[(nf*8+g)*VSTH + ks2*16 + 2*tg + 8]);
                mma_f16(o[nf], a, b0, b1);
            }
        }

        __syncthreads();
        if (j + 2 < 16){
            const int buf = j & 1;
            const __half* kp = Kg + (long)(j+2)*128*QKVC;
            #pragma unroll
            for (int it = 0; it < 4; it++){
                int i = tid + it*256;
                int r = i >> 3, c8 = (i & 7)*8;
                cpa16(&Ks[buf*KBUFH + r*KSTH + c8], kp + (long)r*QKVC + c8);
            }
            #pragma unroll
            for (int it = 0; it < 4; it++){
                int i = tid + it*256;
                int r = i >> 4, c8 = (i & 15)*8;
                cpa16(&Vs[buf*VBUFH + r*VSTH + c8], &Vt[(long)r*N_ + (j+2)*128 + c8]);
            }
            asm volatile("cp.async.commit_group;\n");
        }
    }

    // ---- epilogue: O/l -> fp16 ao ----
    const float inv0 = 1.0f / l0, inv1 = 1.0f / l1;
    __half* o0 = ao + (long)(bb*N_ + q0 + mrow + g  )*D_ + hh*DH_ + 2*tg;
    __half* o1 = ao + (long)(bb*N_ + q0 + mrow + g+8)*D_ + hh*DH_ + 2*tg;
    #pragma unroll
    for (int nf = 0; nf < 8; nf++){
        *reinterpret_cast<unsigned*>(o0 + nf*8) = pk2(o[nf][0]*inv0, o[nf][1]*inv0);
        *reinterpret_cast<unsigned*>(o1 + nf*8) = pk2(o[nf][2]*inv1, o[nf][3]*inv1);
    }
}

// ---------------- fp16 tensor-core GEMM with fused epilogue ------------------
// C = act(A @ Bt^T + bias) + residual.  A [M][K] fp16, Bt [N][K] fp16.
// BM=BN=128, BK=64, 8 warps (WM=64, WN=32). OUTH: fp16 output else fp32.
#define GSTH 72
#define GEMM_SMEM (2*(2*128*GSTH)*2)

template<bool GELU, bool OUTH>
__global__ void __launch_bounds__(256,2)
gemm_h(const __half* __restrict__ A, const __half* __restrict__ Bt,
       const float* __restrict__ bias, const float* __restrict__ residual,
       void* __restrict__ Cv, int K, int lda, int ldb, int ldc)
{
    extern __shared__ __half smg[];
    __half* As = smg;                  // [2][128*GSTH]
    __half* Bs = smg + 2*128*GSTH;     // [2][128*GSTH]

    const int bm = blockIdx.y * 128;
    const int bn = blockIdx.x * 128;
    const int tid  = threadIdx.x;
    const int wid  = tid >> 5, lane = tid & 31;
    const int wm   = wid >> 2, wn = wid & 3;       // 2x4 warp grid
    const int g    = lane >> 2, tg = lane & 3;

    float acc[4][4][4];
    #pragma unroll
    for (int i = 0; i < 4; i++)
        #pragma unroll
        for (int j = 0; j < 4; j++)
            #pragma unroll
            for (int c = 0; c < 4; c++) acc[i][j][c] = 0.f;

    auto issue = [&](int buf, int k0){
        #pragma unroll
        for (int it = 0; it < 4; it++){
            int i = tid + it*256;
            int r = i >> 3, c8 = (i & 7)*8;
            cpa16(&As[buf*128*GSTH + r*GSTH + c8], &A [(long)(bm+r)*lda + k0 + c8]);
        }
        #pragma unroll
        for (int it = 0; it < 4; it++){
            int i = tid + it*256;
            int r = i >> 3, c8 = (i & 7)*8;
            cpa16(&Bs[buf*128*GSTH + r*GSTH + c8], &Bt[(long)(bn+r)*ldb + k0 + c8]);
        }
        asm volatile("cp.async.commit_group;\n");
    };

    const int nIter = K / 64;
    issue(0, 0);

    for (int it = 0; it < nIter; it++){
        const int buf = it & 1;
        if (it + 1 < nIter){
            issue(buf^1, (it+1)*64);
            asm volatile("cp.async.wait_group 1;\n");
        } else {
            asm volatile("cp.async.wait_group 0;\n");
        }
        __syncthreads();
        const __half* Ab = &As[buf*128*GSTH];
        const __half* Bb = &Bs[buf*128*GSTH];

        #pragma unroll
        for (int ks = 0; ks < 4; ks++){
            unsigned a[4][4], b[4][2];
            #pragma unroll
            for (int mf = 0; mf < 4; mf++){
                const int mr = wm*64 + mf*16;
                a[mf][0] = ldh2(&Ab[(mr+g  )*GSTH + ks*16 + 2*tg]);
                a[mf][1] = ldh2(&Ab[(mr+g+8)*GSTH + ks*16 + 2*tg]);
                a[mf][2] = ldh2(&Ab[(mr+g  )*GSTH + ks*16 + 2*tg + 8]);
                a[mf][3] = ldh2(&Ab[(mr+g+8)*GSTH + ks*16 + 2*tg + 8]);
            }
            #pragma unroll
            for (int nf = 0; nf < 4; nf++){
                const int nc = wn*32 + nf*8 + g;
                b[nf][0] = ldh2(&Bb[nc*GSTH + ks*16 + 2*tg]);
                b[nf][1] = ldh2(&Bb[nc*GSTH + ks*16 + 2*tg + 8]);
            }
            #pragma unroll
            for (int mf = 0; mf < 4; mf++)
                #pragma unroll
                for (int nf = 0; nf < 4; nf++)
                    mma_f16(acc[mf][nf], a[mf], b[nf][0], b[nf][1]);
        }
        __syncthreads();
    }

    #pragma unroll
    for (int mf = 0; mf < 4; mf++){
        #pragma unroll
        for (int nf = 0; nf < 4; nf++){
            const int col = bn + wn*32 + nf*8 + tg*2;
            #pragma unroll
            for (int h = 0; h < 2; h++){
                const int row = bm + wm*64 + mf*16 + g + h*8;
                float v0 = acc[mf][nf][h*2+0];
                float v1 = acc[mf][nf][h*2+1];
                if (bias){ v0 += bias[col]; v1 += bias[col+1]; }
                if (GELU){
                    v0 = 0.5f*v0*(1.0f + erff(v0*0.70710678118654752f));
                    v1 = 0.5f*v1*(1.0f + erff(v1*0.70710678118654752f));
                }
                if (residual){
                    v0 += residual[(long)row*ldc + col];
                    v1 += residual[(long)row*ldc + col + 1];
                }
                if (OUTH){
                    *reinterpret_cast<unsigned*>((__half*)Cv + (long)row*ldc + col) = pk2(v0, v1);
                } else {
                    *reinterpret_cast<float2*>((float*)Cv + (long)row*ldc + col) = make_float2(v0, v1);
                }
            }
        }
    }
}

// ---------------------------------------------------------------------------
extern "C" void kernel_launch(void* const* d_in, const int* in_sizes, int n_in,
                              void* d_out, int out_size)
{
    const float* x      = (const float*)d_in[0];
    const float* Wqkv   = (const float*)d_in[1];
    const float* Wout   = (const float*)d_in[2];
    const float* gamma1 = (const float*)d_in[3];
    const float* beta1  = (const float*)d_in[4];
    const float* gamma2 = (const float*)d_in[5];
    const float* beta2  = (const float*)d_in[6];
    const float* W1     = (const float*)d_in[7];
    const float* b1     = (const float*)d_in[8];
    const float* W2     = (const float*)d_in[9];
    const float* b2     = (const float*)d_in[10];
    const float* abias  = (const float*)d_in[11];
    float* out = (float*)d_out;

    __half *h, *qkv, *vt, *ao, *ffn, *wqkvT, *woutT, *w1T, *w2T;
    float *x1;
    cudaGetSymbolAddress((void**)&h,     g_h);
    cudaGetSymbolAddress((void**)&qkv,   g_qkv);
    cudaGetSymbolAddress((void**)&vt,    g_vt);
    cudaGetSymbolAddress((void**)&ao,    g_ao);
    cudaGetSymbolAddress((void**)&x1,    g_x1);
    cudaGetSymbolAddress((void**)&ffn,   g_ffn);
    cudaGetSymbolAddress((void**)&wqkvT, g_wqkvT);
    cudaGetSymbolAddress((void**)&woutT, g_woutT);
    cudaGetSymbolAddress((void**)&w1T,   g_w1T);
    cudaGetSymbolAddress((void**)&w2T,   g_w2T);

    cudaFuncSetAttribute(flash_kernel, cudaFuncAttributeMaxDynamicSharedMemorySize, FA_SMEM);
    cudaFuncSetAttribute(gemm_h<false,true>,  cudaFuncAttributeMaxDynamicSharedMemorySize, GEMM_SMEM);
    cudaFuncSetAttribute(gemm_h<false,false>, cudaFuncAttributeMaxDynamicSharedMemorySize, GEMM_SMEM);
    cudaFuncSetAttribute(gemm_h<true,true>,   cudaFuncAttributeMaxDynamicSharedMemorySize, GEMM_SMEM);

    // 0. weights -> fp16 transposed
    convT<<<dim3(QKVC/32, D_/32), dim3(32,8)>>>(Wqkv, wqkvT, D_, QKVC);
    convT<<<dim3(D_/32,   D_/32), dim3(32,8)>>>(Wout, woutT, D_, D_);
    convT<<<dim3(M_/32,   D_/32), dim3(32,8)>>>(W1,   w1T,   D_, M_);
    convT<<<dim3(D_/32,   M_/32), dim3(32,8)>>>(W2,   w2T,   M_, D_);

    // 1. h = LN(x)
    ln_kernel<<<R_, 256>>>(x, gamma1, beta1, h);

    // 2. qkv = h @ Wqkv  (fp16 out)
    gemm_h<false,true><<<dim3(QKVC/128, R_/128), 256, GEMM_SMEM>>>(
        h, wqkvT, nullptr, nullptr, qkv, D_, D_, D_, QKVC);

    // 2b. vt = V transposed per head
    vtrans<<<dim3(N_/32, 2*H_*B_), dim3(32,8)>>>(qkv, vt);

    // 3-5. flash attention -> ao (fp16)
    flash_kernel<<<dim3(N_/128, H_, B_), 256, FA_SMEM>>>(qkv, vt, abias, ao);

    // 6. x1 = ao @ Wout + x  (fp32 out)
    gemm_h<false,false><<<dim3(D_/128, R_/128), 256, GEMM_SMEM>>>(
        ao, woutT, nullptr, x, x1, D_, D_, D_, D_);

    // 7. h = LN(x1)
    ln_kernel<<<R_, 256>>>(x1, gamma2, beta2, h);

    // 8. ffn = gelu(h @ W1 + b1)  (fp16 out)
    gemm_h<true,true><<<dim3(M_/128, R_/128), 256, GEMM_SMEM>>>(
        h, w1T, b1, nullptr, ffn, D_, D_, D_, M_);

    // 9. out = ffn @ W2 + b2 + x1  (fp32 out)
    gemm_h<false,false><<<dim3(D_/128, R_/128), 256, GEMM_SMEM>>>(
        ffn, w2T, b2, x1, out, M_, M_, M_, D_);
}

// round 7
// speedup vs baseline: 1.9476x; 1.0427x over previous
#include <cuda_runtime.h>
#include <cuda_fp16.h>
#include <math.h>

#define B_   2
#define N_   2048
#define D_   768
#define H_   12
#define DH_  64
#define M_   3072
#define R_   (B_*N_)
#define QKVC (3*H_*DH_)

// ---------------- scratch (device globals) ----------------------------------
__device__ __half g_h[(size_t)R_*D_];
__device__ __half g_qkv[(size_t)R_*QKVC];
__device__ __half g_vt[(size_t)B_*H_*DH_*N_];
__device__ __half g_ao[(size_t)R_*D_];
__device__ float  g_x1[(size_t)R_*D_];
__device__ __half g_ffn[(size_t)R_*M_];
__device__ __half g_wqkvT[(size_t)QKVC*D_];
__device__ __half g_woutT[(size_t)D_*D_];
__device__ __half g_w1T[(size_t)M_*D_];
__device__ __half g_w2T[(size_t)D_*M_];

// ---------------- helpers ----------------------------------------------------
__device__ __forceinline__ void cpa16(void* dst, const void* src){
    unsigned d = (unsigned)__cvta_generic_to_shared(dst);
    asm volatile("cp.async.cg.shared.global [%0], [%1], 16;\n" :: "r"(d), "l"(src));
}
__device__ __forceinline__ void mma_f16(float* c, const unsigned* a, unsigned b0, unsigned b1){
    asm volatile("mma.sync.aligned.m16n8k16.row.col.f32.f16.f16.f32 "
        "{%0,%1,%2,%3}, {%4,%5,%6,%7}, {%8,%9}, {%0,%1,%2,%3};\n"
        : "+f"(c[0]),"+f"(c[1]),"+f"(c[2]),"+f"(c[3])
        : "r"(a[0]),"r"(a[1]),"r"(a[2]),"r"(a[3]), "r"(b0),"r"(b1));
}
__device__ __forceinline__ void ldsm4(unsigned* r, const __half* p){
    unsigned addr = (unsigned)__cvta_generic_to_shared(p);
    asm volatile("ldmatrix.sync.aligned.m8n8.x4.shared.b16 {%0,%1,%2,%3}, [%4];"
        : "=r"(r[0]),"=r"(r[1]),"=r"(r[2]),"=r"(r[3]) : "r"(addr));
}
__device__ __forceinline__ unsigned pk2(float a, float b){
    __half2 h = __floats2half2_rn(a, b);
    return *reinterpret_cast<unsigned*>(&h);
}

// ---------------- weight convert+transpose: [K][N] fp32 -> [N][K] fp16 ------
__global__ void convT(const float* __restrict__ in, __half* __restrict__ out, int K, int N)
{
    __shared__ float t[32][33];
    const int n0 = blockIdx.x*32, k0 = blockIdx.y*32;
    #pragma unroll
    for (int i = 0; i < 4; i++)
        t[threadIdx.y + i*8][threadIdx.x] =
            in[(long)(k0 + threadIdx.y + i*8)*N + n0 + threadIdx.x];
    __syncthreads();
    #pragma unroll
    for (int i = 0; i < 4; i++)
        out[(long)(n0 + threadIdx.y + i*8)*K + k0 + threadIdx.x] =
            __float2half_rn(t[threadIdx.x][threadIdx.y + i*8]);
}

// ---------------- V transpose: qkv fp16 -> vt[b][h][dh][token] ---------------
__global__ void vtrans(const __half* __restrict__ qkv, __half* __restrict__ vt)
{
    __shared__ __half t[32][34];
    const int n0 = blockIdx.x*32;
    const int yy = blockIdx.y;
    const int d0 = (yy & 1)*32;
    const int hh = (yy >> 1) % H_;
    const int bb = yy / (2*H_);
    #pragma unroll
    for (int i = 0; i < 4; i++)
        t[threadIdx.y + i*8][threadIdx.x] =
            qkv[(long)(bb*N_ + n0 + threadIdx.y + i*8)*QKVC + 2*H_*DH_ + hh*DH_ + d0 + threadIdx.x];
    __syncthreads();
    #pragma unroll
    for (int i = 0; i < 4; i++)
        vt[(long)((bb*H_ + hh)*DH_ + d0 + threadIdx.y + i*8)*N_ + n0 + threadIdx.x] =
            t[threadIdx.x][threadIdx.y + i*8];
}

// ---------------- LayerNorm: fp32 in -> fp16 out -----------------------------
__global__ void ln_kernel(const float* __restrict__ x,
                          const float* __restrict__ gamma,
                          const float* __restrict__ beta,
                          __half* __restrict__ out)
{
    const int row = blockIdx.x;
    const float* xr = x + (long)row * D_;
    float v[3];
    float s = 0.f, s2 = 0.f;
    #pragma unroll
    for (int i = 0; i < 3; i++) {
        v[i] = xr[threadIdx.x + i*256];
        s  += v[i];
        s2 += v[i]*v[i];
    }
    #pragma unroll
    for (int o = 16; o > 0; o >>= 1) {
        s  += __shfl_xor_sync(0xffffffffu, s,  o);
        s2 += __shfl_xor_sync(0xffffffffu, s2, o);
    }
    __shared__ float sa[8], sb[8];
    int w = threadIdx.x >> 5, l = threadIdx.x & 31;
    if (l == 0) { sa[w] = s; sb[w] = s2; }
    __syncthreads();
    s = 0.f; s2 = 0.f;
    #pragma unroll
    for (int i = 0; i < 8; i++) { s += sa[i]; s2 += sb[i]; }

    const float mean = s * (1.0f / D_);
    const float var  = s2 * (1.0f / D_) - mean*mean;
    const float rstd = rsqrtf(var + 1e-5f);
    __half* o = out + (long)row * D_;
    #pragma unroll
    for (int i = 0; i < 3; i++) {
        int c = threadIdx.x + i*256;
        o[c] = __float2half_rn((v[i] - mean) * rstd * gamma[c] + beta[c]);
    }
}

// ---------------- Flash attention (fp16 + ldmatrix) --------------------------
#define KSTH 72
#define VSTH 136
#define PSTH 136
#define KBUFH (128*KSTH)
#define VBUFH (64*VSTH)
#define VS_OFFH (2*KBUFH)
#define PS_OFFH (2*KBUFH + 2*VBUFH)
#define FA_SMEM ((2*KBUFH + 2*VBUFH + 128*PSTH)*2)

__global__ void __launch_bounds__(256,1)
flash_kernel(const __half* __restrict__ qkv,
             const __half* __restrict__ vt,
             const float* __restrict__ bias,
             __half* __restrict__ ao)
{
    extern __shared__ __half smh[];
    __half* Ks = smh;
    __half* Vs = smh + VS_OFFH;
    __half* Ps = smh + PS_OFFH;

    const int qt = blockIdx.x, hh = blockIdx.y, bb = blockIdx.z;
    const int q0 = qt*128;
    const long base = (long)bb*N_*QKVC;
    const __half* Qg = qkv + base + hh*DH_;
    const __half* Kg = qkv + base + H_*DH_ + hh*DH_;
    const __half* Vt = vt + (long)(bb*H_ + hh)*DH_*N_;
    const float* Bg = bias + (long)hh*N_*N_;

    const int tid = threadIdx.x, wid = tid>>5, lane = tid&31;
    const int g = lane>>2, tg = lane&3;
    const int mrow = wid*16;
    const int li = lane >> 3;            // ldmatrix matrix index 0..3
    const int lr = lane & 7;             // row within 8x8 tile
    const int arow = (li&1)*8 + lr;      // A-operand row offset
    const int acol = (li>>1)*8;          // A-operand k offset
    const int bqrow = (li>>1)*8 + lr;    // B-operand n offset
    const int bqcol = (li&1)*8;          // B-operand k offset

    // prologue: group0 = {Q, K0, V0}, group1 = {K1, V1}
    {
        #pragma unroll
        for (int it = 0; it < 4; it++){
            int i = tid + it*256;
            int r = i >> 3, c8 = (i & 7)*8;
            cpa16(&Ps[r*KSTH + c8], &Qg[(long)(q0+r)*QKVC + c8]);
            cpa16(&Ks[r*KSTH + c8], &Kg[(long)r*QKVC + c8]);
        }
        #pragma unroll
        for (int it = 0; it < 4; it++){
            int i = tid + it*256;
            int r = i >> 4, c8 = (i & 15)*8;
            cpa16(&Vs[r*VSTH + c8], &Vt[(long)r*N_ + c8]);
        }
        asm volatile("cp.async.commit_group;\n");
        #pragma unroll
        for (int it = 0; it < 4; it++){
            int i = tid + it*256;
            int r = i >> 3, c8 = (i & 7)*8;
            cpa16(&Ks[KBUFH + r*KSTH + c8], &Kg[(long)(128+r)*QKVC + c8]);
        }
        #pragma unroll
        for (int it = 0; it < 4; it++){
            int i = tid + it*256;
            int r = i >> 4, c8 = (i & 15)*8;
            cpa16(&Vs[VBUFH + r*VSTH + c8], &Vt[(long)r*N_ + 128 + c8]);
        }
        asm volatile("cp.async.commit_group;\n");
    }

    asm volatile("cp.async.wait_group 1;\n");
    __syncthreads();

    // Q fragments (loop-invariant): 4 k-steps of 16, A-operand ldmatrix
    unsigned qf[4][4];
    #pragma unroll
    for (int ks = 0; ks < 4; ks++)
        ldsm4(qf[ks], &Ps[(mrow + arow)*KSTH + ks*16 + acol]);
    __syncwarp();

    float m0 = -1e30f, m1 = -1e30f, l0 = 0.f, l1 = 0.f;
    float o[8][4];
    #pragma unroll
    for (int i = 0; i < 8; i++)
        #pragma unroll
        for (int c = 0; c < 4; c++) o[i][c] = 0.f;

    for (int j = 0; j < 16; j++){
        if (j < 15) asm volatile("cp.async.wait_group 1;\n");
        else        asm volatile("cp.async.wait_group 0;\n");
        __syncthreads();
        const __half* Kb = &Ks[(j&1)*KBUFH];
        const __half* Vb = &Vs[(j&1)*VBUFH];

        // ---- S = Q @ K^T ----
        float s[16][4];
        #pragma unroll
        for (int nf = 0; nf < 16; nf++)
            #pragma unroll
            for (int c = 0; c < 4; c++) s[nf][c] = 0.f;
        #pragma unroll
        for (int nf2 = 0; nf2 < 8; nf2++){
            #pragma unroll
            for (int ks = 0; ks < 4; ks++){
                unsigned kb[4];
                ldsm4(kb, &Kb[(nf2*16 + bqrow)*KSTH + ks*16 + bqcol]);
                mma_f16(s[2*nf2+0], qf[ks], kb[0], kb[1]);
                mma_f16(s[2*nf2+1], qf[ks], kb[2], kb[3]);
            }
        }

        // ---- scale + bias ----
        const float* br0 = Bg + (long)(q0+mrow+g  )*N_ + j*128 + 2*tg;
        const float* br1 = Bg + (long)(q0+mrow+g+8)*N_ + j*128 + 2*tg;
        #pragma unroll
        for (int nf = 0; nf < 16; nf++){
            float2 t0 = *reinterpret_cast<const float2*>(br0 + nf*8);
            float2 t1 = *reinterpret_cast<const float2*>(br1 + nf*8);
            s[nf][0] = fmaf(s[nf][0], 0.125f, t0.x);
            s[nf][1] = fmaf(s[nf][1], 0.125f, t0.y);
            s[nf][2] = fmaf(s[nf][2], 0.125f, t1.x);
            s[nf][3] = fmaf(s[nf][3], 0.125f, t1.y);
        }

        // ---- online softmax ----
        float mt0 = -1e30f, mt1 = -1e30f;
        #pragma unroll
        for (int nf = 0; nf < 16; nf++){
            mt0 = fmaxf(mt0, fmaxf(s[nf][0], s[nf][1]));
            mt1 = fmaxf(mt1, fmaxf(s[nf][2], s[nf][3]));
        }
        mt0 = fmaxf(mt0, __shfl_xor_sync(0xffffffffu, mt0, 1));
        mt0 = fmaxf(mt0, __shfl_xor_sync(0xffffffffu, mt0, 2));
        mt1 = fmaxf(mt1, __shfl_xor_sync(0xffffffffu, mt1, 1));
        mt1 = fmaxf(mt1, __shfl_xor_sync(0xffffffffu, mt1, 2));
        const float mn0 = fmaxf(m0, mt0), mn1 = fmaxf(m1, mt1);
        const float cr0 = __expf(m0 - mn0), cr1 = __expf(m1 - mn1);
        m0 = mn0; m1 = mn1;

        float ls0 = 0.f, ls1 = 0.f;
        __half* pr0 = &Ps[(mrow+g  )*PSTH + 2*tg];
        __half* pr1 = &Ps[(mrow+g+8)*PSTH + 2*tg];
        #pragma unroll
        for (int nf = 0; nf < 16; nf++){
            float p0 = __expf(s[nf][0] - m0);
            float p1 = __expf(s[nf][1] - m0);
            float p2 = __expf(s[nf][2] - m1);
            float p3 = __expf(s[nf][3] - m1);
            ls0 += p0 + p1; ls1 += p2 + p3;
            *reinterpret_cast<unsigned*>(pr0 + nf*8) = pk2(p0, p1);
            *reinterpret_cast<unsigned*>(pr1 + nf*8) = pk2(p2, p3);
        }
        ls0 += __shfl_xor_sync(0xffffffffu, ls0, 1);
        ls0 += __shfl_xor_sync(0xffffffffu, ls0, 2);
        ls1 += __shfl_xor_sync(0xffffffffu, ls1, 1);
        ls1 += __shfl_xor_sync(0xffffffffu, ls1, 2);
        l0 = l0*cr0 + ls0;
        l1 = l1*cr1 + ls1;
        #pragma unroll
        for (int nf = 0; nf < 8; nf++){
            o[nf][0] *= cr0; o[nf][1] *= cr0;
            o[nf][2] *= cr1; o[nf][3] *= cr1;
        }
        __syncwarp();

        // ---- O += P @ V ----   (V in [dh][token] layout)
        #pragma unroll
        for (int ks2 = 0; ks2 < 8; ks2++){
            unsigned a[4];
            ldsm4(a, &Ps[(mrow + arow)*PSTH + ks2*16 + acol]);
            #pragma unroll
            for (int nf2 = 0; nf2 < 4; nf2++){
                unsigned vb[4];
                ldsm4(vb, &Vb[(nf2*16 + bqrow)*VSTH + ks2*16 + bqcol]);
                mma_f16(o[2*nf2+0], a, vb[0], vb[1]);
                mma_f16(o[2*nf2+1], a, vb[2], vb[3]);
            }
        }

        __syncthreads();
        if (j + 2 < 16){
            const int buf = j & 1;
            const __half* kp = Kg + (long)(j+2)*128*QKVC;
            #pragma unroll
            for (int it = 0; it < 4; it++){
                int i = tid + it*256;
                int r = i >> 3, c8 = (i & 7)*8;
                cpa16(&Ks[buf*KBUFH + r*KSTH + c8], kp + (long)r*QKVC + c8);
            }
            #pragma unroll
            for (int it = 0; it < 4; it++){
                int i = tid + it*256;
                int r = i >> 4, c8 = (i & 15)*8;
                cpa16(&Vs[buf*VBUFH + r*VSTH + c8], &Vt[(long)r*N_ + (j+2)*128 + c8]);
            }
            asm volatile("cp.async.commit_group;\n");
        }
    }

    // ---- epilogue: O/l -> fp16 ao ----
    const float inv0 = 1.0f / l0, inv1 = 1.0f / l1;
    __half* o0 = ao + (long)(bb*N_ + q0 + mrow + g  )*D_ + hh*DH_ + 2*tg;
    __half* o1 = ao + (long)(bb*N_ + q0 + mrow + g+8)*D_ + hh*DH_ + 2*tg;
    #pragma unroll
    for (int nf = 0; nf < 8; nf++){
        *reinterpret_cast<unsigned*>(o0 + nf*8) = pk2(o[nf][0]*inv0, o[nf][1]*inv0);
        *reinterpret_cast<unsigned*>(o1 + nf*8) = pk2(o[nf][2]*inv1, o[nf][3]*inv1);
    }
}

// ---------------- fp16 tensor-core GEMM with fused epilogue ------------------
// C = act(A @ Bt^T + bias) + residual.  A [M][K] fp16, Bt [N][K] fp16.
#define GSTH 72
#define GEMM_SMEM (2*(2*128*GSTH)*2)

template<bool GELU, bool OUTH>
__global__ void __launch_bounds__(256,2)
gemm_h(const __half* __restrict__ A, const __half* __restrict__ Bt,
       const float* __restrict__ bias, const float* __restrict__ residual,
       void* __restrict__ Cv, int K, int lda, int ldb, int ldc)
{
    extern __shared__ __half smg[];
    __half* As = smg;
    __half* Bs = smg + 2*128*GSTH;

    const int bm = blockIdx.y * 128;
    const int bn = blockIdx.x * 128;
    const int tid  = threadIdx.x;
    const int wid  = tid >> 5, lane = tid & 31;
    const int wm   = wid >> 2, wn = wid & 3;
    const int g    = lane >> 2, tg = lane & 3;
    const int li = lane >> 3, lr = lane & 7;
    const int arow = (li&1)*8 + lr, acol = (li>>1)*8;
    const int brow = (li>>1)*8 + lr, bcol = (li&1)*8;

    float acc[4][4][4];
    #pragma unroll
    for (int i = 0; i < 4; i++)
        #pragma unroll
        for (int j = 0; j < 4; j++)
            #pragma unroll
            for (int c = 0; c < 4; c++) acc[i][j][c] = 0.f;

    auto issue = [&](int buf, int k0){
        #pragma unroll
        for (int it = 0; it < 4; it++){
            int i = tid + it*256;
            int r = i >> 3, c8 = (i & 7)*8;
            cpa16(&As[buf*128*GSTH + r*GSTH + c8], &A [(long)(bm+r)*lda + k0 + c8]);
        }
        #pragma unroll
        for (int it = 0; it < 4; it++){
            int i = tid + it*256;
            int r = i >> 3, c8 = (i & 7)*8;
            cpa16(&Bs[buf*128*GSTH + r*GSTH + c8], &Bt[(long)(bn+r)*ldb + k0 + c8]);
        }
        asm volatile("cp.async.commit_group;\n");
    };

    const int nIter = K / 64;
    issue(0, 0);

    for (int it = 0; it < nIter; it++){
        const int buf = it & 1;
        if (it + 1 < nIter){
            issue(buf^1, (it+1)*64);
            asm volatile("cp.async.wait_group 1;\n");
        } else {
            asm volatile("cp.async.wait_group 0;\n");
        }
        __syncthreads();
        const __half* Ab = &As[buf*128*GSTH];
        const __half* Bb = &Bs[buf*128*GSTH];

        #pragma unroll
        for (int ks = 0; ks < 4; ks++){
            unsigned a[4][4], b[2][4];
            #pragma unroll
            for (int mf = 0; mf < 4; mf++)
                ldsm4(a[mf], &Ab[(wm*64 + mf*16 + arow)*GSTH + ks*16 + acol]);
            #pragma unroll
            for (int nf2 = 0; nf2 < 2; nf2++)
                ldsm4(b[nf2], &Bb[(wn*32 + nf2*16 + brow)*GSTH + ks*16 + bcol]);
            #pragma unroll
            for (int mf = 0; mf < 4; mf++){
                #pragma unroll
                for (int nf2 = 0; nf2 < 2; nf2++){
                    mma_f16(acc[mf][2*nf2+0], a[mf], b[nf2][0], b[nf2][1]);
                    mma_f16(acc[mf][2*nf2+1], a[mf], b[nf2][2], b[nf2][3]);
                }
            }
        }
        __syncthreads();
    }

    #pragma unroll
    for (int mf = 0; mf < 4; mf++){
        #pragma unroll
        for (int nf = 0; nf < 4; nf++){
            const int col = bn + wn*32 + nf*8 + tg*2;
            #pragma unroll
            for (int h = 0; h < 2; h++){
                const int row = bm + wm*64 + mf*16 + g + h*8;
                float v0 = acc[mf][nf][h*2+0];
                float v1 = acc[mf][nf][h*2+1];
                if (bias){ v0 += bias[col]; v1 += bias[col+1]; }
                if (GELU){
                    v0 = 0.5f*v0*(1.0f + erff(v0*0.70710678118654752f));
                    v1 = 0.5f*v1*(1.0f + erff(v1*0.70710678118654752f));
                }
                if (residual){
                    v0 += residual[(long)row*ldc + col];
                    v1 += residual[(long)row*ldc + col + 1];
                }
                if (OUTH){
                    *reinterpret_cast<unsigned*>((__half*)Cv + (long)row*ldc + col) = pk2(v0, v1);
                } else {
                    *reinterpret_cast<float2*>((float*)Cv + (long)row*ldc + col) = make_float2(v0, v1);
                }
            }
        }
    }
}

// ---------------------------------------------------------------------------
extern "C" void kernel_launch(void* const* d_in, const int* in_sizes, int n_in,
                              void* d_out, int out_size)
{
    const float* x      = (const float*)d_in[0];
    const float* Wqkv   = (const float*)d_in[1];
    const float* Wout   = (const float*)d_in[2];
    const float* gamma1 = (const float*)d_in[3];
    const float* beta1  = (const float*)d_in[4];
    const float* gamma2 = (const float*)d_in[5];
    const float* beta2  = (const float*)d_in[6];
    const float* W1     = (const float*)d_in[7];
    const float* b1     = (const float*)d_in[8];
    const float* W2     = (const float*)d_in[9];
    const float* b2     = (const float*)d_in[10];
    const float* abias  = (const float*)d_in[11];
    float* out = (float*)d_out;

    __half *h, *qkv, *vt, *ao, *ffn, *wqkvT, *woutT, *w1T, *w2T;
    float *x1;
    cudaGetSymbolAddress((void**)&h,     g_h);
    cudaGetSymbolAddress((void**)&qkv,   g_qkv);
    cudaGetSymbolAddress((void**)&vt,    g_vt);
    cudaGetSymbolAddress((void**)&ao,    g_ao);
    cudaGetSymbolAddress((void**)&x1,    g_x1);
    cudaGetSymbolAddress((void**)&ffn,   g_ffn);
    cudaGetSymbolAddress((void**)&wqkvT, g_wqkvT);
    cudaGetSymbolAddress((void**)&woutT, g_woutT);
    cudaGetSymbolAddress((void**)&w1T,   g_w1T);
    cudaGetSymbolAddress((void**)&w2T,   g_w2T);

    cudaFuncSetAttribute(flash_kernel, cudaFuncAttributeMaxDynamicSharedMemorySize, FA_SMEM);
    cudaFuncSetAttribute(gemm_h<false,true>,  cudaFuncAttributeMaxDynamicSharedMemorySize, GEMM_SMEM);
    cudaFuncSetAttribute(gemm_h<false,false>, cudaFuncAttributeMaxDynamicSharedMemorySize, GEMM_SMEM);
    cudaFuncSetAttribute(gemm_h<true,true>,   cudaFuncAttributeMaxDynamicSharedMemorySize, GEMM_SMEM);

    // 0. weights -> fp16 transposed
    convT<<<dim3(QKVC/32, D_/32), dim3(32,8)>>>(Wqkv, wqkvT, D_, QKVC);
    convT<<<dim3(D_/32,   D_/32), dim3(32,8)>>>(Wout, woutT, D_, D_);
    convT<<<dim3(M_/32,   D_/32), dim3(32,8)>>>(W1,   w1T,   D_, M_);
    convT<<<dim3(D_/32,   M_/32), dim3(32,8)>>>(W2,   w2T,   M_, D_);

    // 1. h = LN(x)
    ln_kernel<<<R_, 256>>>(x, gamma1, beta1, h);

    // 2. qkv = h @ Wqkv  (fp16 out)
    gemm_h<false,true><<<dim3(QKVC/128, R_/128), 256, GEMM_SMEM>>>(
        h, wqkvT, nullptr, nullptr, qkv, D_, D_, D_, QKVC);

    // 2b. vt = V transposed per head
    vtrans<<<dim3(N_/32, 2*H_*B_), dim3(32,8)>>>(qkv, vt);

    // 3-5. flash attention -> ao (fp16)
    flash_kernel<<<dim3(N_/128, H_, B_), 256, FA_SMEM>>>(qkv, vt, abias, ao);

    // 6. x1 = ao @ Wout + x  (fp32 out)
    gemm_h<false,false><<<dim3(D_/128, R_/128), 256, GEMM_SMEM>>>(
        ao, woutT, nullptr, x, x1, D_, D_, D_, D_);

    // 7. h = LN(x1)
    ln_kernel<<<R_, 256>>>(x1, gamma2, beta2, h);

    // 8. ffn = gelu(h @ W1 + b1)  (fp16 out)
    gemm_h<true,true><<<dim3(M_/128, R_/128), 256, GEMM_SMEM>>>(
        h, w1T, b1, nullptr, ffn, D_, D_, D_, M_);

    // 9. out = ffn @ W2 + b2 + x1  (fp32 out)
    gemm_h<false,false><<<dim3(D_/128, R_/128), 256, GEMM_SMEM>>>(
        ffn, w2T, b2, x1, out, M_, M_, M_, D_);
}

// round 8
// speedup vs baseline: 1.9479x; 1.0002x over previous
#include <cuda_runtime.h>
#include <cuda_fp16.h>
#include <math.h>

#define B_   2
#define N_   2048
#define D_   768
#define H_   12
#define DH_  64
#define M_   3072
#define R_   (B_*N_)
#define QKVC (3*H_*DH_)

// ---------------- scratch (device globals) ----------------------------------
__device__ __half g_h[(size_t)R_*D_];
__device__ __half g_qkv[(size_t)R_*QKVC];
__device__ __half g_vt[(size_t)B_*H_*DH_*N_];
__device__ __half g_ao[(size_t)R_*D_];
__device__ float  g_x1[(size_t)R_*D_];
__device__ __half g_ffn[(size_t)R_*M_];
__device__ __half g_wqkvT[(size_t)QKVC*D_];
__device__ __half g_woutT[(size_t)D_*D_];
__device__ __half g_w1T[(size_t)M_*D_];
__device__ __half g_w2T[(size_t)D_*M_];

// ---------------- helpers ----------------------------------------------------
__device__ __forceinline__ void cpa16(void* dst, const void* src){
    unsigned d = (unsigned)__cvta_generic_to_shared(dst);
    asm volatile("cp.async.cg.shared.global [%0], [%1], 16;\n" :: "r"(d), "l"(src));
}
__device__ __forceinline__ void mma_f16(float* c, const unsigned* a, unsigned b0, unsigned b1){
    asm volatile("mma.sync.aligned.m16n8k16.row.col.f32.f16.f16.f32 "
        "{%0,%1,%2,%3}, {%4,%5,%6,%7}, {%8,%9}, {%0,%1,%2,%3};\n"
        : "+f"(c[0]),"+f"(c[1]),"+f"(c[2]),"+f"(c[3])
        : "r"(a[0]),"r"(a[1]),"r"(a[2]),"r"(a[3]), "r"(b0),"r"(b1));
}
__device__ __forceinline__ void ldsm4(unsigned* r, const __half* p){
    unsigned addr = (unsigned)__cvta_generic_to_shared(p);
    asm volatile("ldmatrix.sync.aligned.m8n8.x4.shared.b16 {%0,%1,%2,%3}, [%4];"
        : "=r"(r[0]),"=r"(r[1]),"=r"(r[2]),"=r"(r[3]) : "r"(addr));
}
__device__ __forceinline__ unsigned pk2(float a, float b){
    __half2 h = __floats2half2_rn(a, b);
    return *reinterpret_cast<unsigned*>(&h);
}

// ---------------- weight convert+transpose: [K][N] fp32 -> [N][K] fp16 ------
__global__ void convT(const float* __restrict__ in, __half* __restrict__ out, int K, int N)
{
    __shared__ float t[32][33];
    const int n0 = blockIdx.x*32, k0 = blockIdx.y*32;
    #pragma unroll
    for (int i = 0; i < 4; i++)
        t[threadIdx.y + i*8][threadIdx.x] =
            in[(long)(k0 + threadIdx.y + i*8)*N + n0 + threadIdx.x];
    __syncthreads();
    #pragma unroll
    for (int i = 0; i < 4; i++)
        out[(long)(n0 + threadIdx.y + i*8)*K + k0 + threadIdx.x] =
            __float2half_rn(t[threadIdx.x][threadIdx.y + i*8]);
}

// ---------------- V transpose: qkv fp16 -> vt[b][h][dh][token] ---------------
__global__ void vtrans(const __half* __restrict__ qkv, __half* __restrict__ vt)
{
    __shared__ __half t[32][34];
    const int n0 = blockIdx.x*32;
    const int yy = blockIdx.y;
    const int d0 = (yy & 1)*32;
    const int hh = (yy >> 1) % H_;
    const int bb = yy / (2*H_);
    #pragma unroll
    for (int i = 0; i < 4; i++)
        t[threadIdx.y + i*8][threadIdx.x] =
            qkv[(long)(bb*N_ + n0 + threadIdx.y + i*8)*QKVC + 2*H_*DH_ + hh*DH_ + d0 + threadIdx.x];
    __syncthreads();
    #pragma unroll
    for (int i = 0; i < 4; i++)
        vt[(long)((bb*H_ + hh)*DH_ + d0 + threadIdx.y + i*8)*N_ + n0 + threadIdx.x] =
            t[threadIdx.x][threadIdx.y + i*8];
}

// ---------------- LayerNorm: fp32 in -> fp16 out -----------------------------
__global__ void ln_kernel(const float* __restrict__ x,
                          const float* __restrict__ gamma,
                          const float* __restrict__ beta,
                          __half* __restrict__ out)
{
    const int row = blockIdx.x;
    const float* xr = x + (long)row * D_;
    float v[3];
    float s = 0.f, s2 = 0.f;
    #pragma unroll
    for (int i = 0; i < 3; i++) {
        v[i] = xr[threadIdx.x + i*256];
        s  += v[i];
        s2 += v[i]*v[i];
    }
    #pragma unroll
    for (int o = 16; o > 0; o >>= 1) {
        s  += __shfl_xor_sync(0xffffffffu, s,  o);
        s2 += __shfl_xor_sync(0xffffffffu, s2, o);
    }
    __shared__ float sa[8], sb[8];
    int w = threadIdx.x >> 5, l = threadIdx.x & 31;
    if (l == 0) { sa[w] = s; sb[w] = s2; }
    __syncthreads();
    s = 0.f; s2 = 0.f;
    #pragma unroll
    for (int i = 0; i < 8; i++) { s += sa[i]; s2 += sb[i]; }

    const float mean = s * (1.0f / D_);
    const float var  = s2 * (1.0f / D_) - mean*mean;
    const float rstd = rsqrtf(var + 1e-5f);
    __half* o = out + (long)row * D_;
    #pragma unroll
    for (int i = 0; i < 3; i++) {
        int c = threadIdx.x + i*256;
        o[c] = __float2half_rn((v[i] - mean) * rstd * gamma[c] + beta[c]);
    }
}

// ---------------- Flash attention (fp16 + ldmatrix, 3-stage) -----------------
#define KSTH 72
#define VSTH 136
#define PSTH 136
#define KBUFH (128*KSTH)
#define VBUFH (64*VSTH)
#define VS_OFFH (3*KBUFH)
#define PS_OFFH (3*KBUFH + 3*VBUFH)
#define FA_SMEM ((3*KBUFH + 3*VBUFH + 128*PSTH)*2)

__global__ void __launch_bounds__(256,1)
flash_kernel(const __half* __restrict__ qkv,
             const __half* __restrict__ vt,
             const float* __restrict__ bias,
             __half* __restrict__ ao)
{
    extern __shared__ __half smh[];
    __half* Ks = smh;
    __half* Vs = smh + VS_OFFH;
    __half* Ps = smh + PS_OFFH;

    const int qt = blockIdx.x, hh = blockIdx.y, bb = blockIdx.z;
    const int q0 = qt*128;
    const long base = (long)bb*N_*QKVC;
    const __half* Qg = qkv + base + hh*DH_;
    const __half* Kg = qkv + base + H_*DH_ + hh*DH_;
    const __half* Vt = vt + (long)(bb*H_ + hh)*DH_*N_;
    const float* Bg = bias + (long)hh*N_*N_;

    const int tid = threadIdx.x, wid = tid>>5, lane = tid&31;
    const int g = lane>>2, tg = lane&3;
    const int mrow = wid*16;
    const int li = lane >> 3, lr = lane & 7;
    const int arow = (li&1)*8 + lr;
    const int acol = (li>>1)*8;
    const int bqrow = (li>>1)*8 + lr;
    const int bqcol = (li&1)*8;

    // loader for K/V tile j into stage st
    auto loadKV = [&](int st, int j){
        const __half* kp = Kg + (long)j*128*QKVC;
        #pragma unroll
        for (int it = 0; it < 4; it++){
            int i = tid + it*256;
            int r = i >> 3, c8 = (i & 7)*8;
            cpa16(&Ks[st*KBUFH + r*KSTH + c8], kp + (long)r*QKVC + c8);
        }
        #pragma unroll
        for (int it = 0; it < 4; it++){
            int i = tid + it*256;
            int r = i >> 4, c8 = (i & 15)*8;
            cpa16(&Vs[st*VBUFH + r*VSTH + c8], &Vt[(long)r*N_ + j*128 + c8]);
        }
        asm volatile("cp.async.commit_group;\n");
    };

    // prologue: group0 = {Q, K0, V0}, group1 = {K1, V1}
    {
        #pragma unroll
        for (int it = 0; it < 4; it++){
            int i = tid + it*256;
            int r = i >> 3, c8 = (i & 7)*8;
            cpa16(&Ps[r*KSTH + c8], &Qg[(long)(q0+r)*QKVC + c8]);
            cpa16(&Ks[r*KSTH + c8], &Kg[(long)r*QKVC + c8]);
        }
        #pragma unroll
        for (int it = 0; it < 4; it++){
            int i = tid + it*256;
            int r = i >> 4, c8 = (i & 15)*8;
            cpa16(&Vs[r*VSTH + c8], &Vt[(long)r*N_ + c8]);
        }
        asm volatile("cp.async.commit_group;\n");
        loadKV(1, 1);
    }

    asm volatile("cp.async.wait_group 1;\n");
    __syncthreads();

    // Q fragments (loop-invariant)
    unsigned qf[4][4];
    #pragma unroll
    for (int ks = 0; ks < 4; ks++)
        ldsm4(qf[ks], &Ps[(mrow + arow)*KSTH + ks*16 + acol]);
    __syncwarp();

    float m0 = -1e30f, m1 = -1e30f, l0 = 0.f, l1 = 0.f;
    float o[8][4];
    #pragma unroll
    for (int i = 0; i < 8; i++)
        #pragma unroll
        for (int c = 0; c < 4; c++) o[i][c] = 0.f;

    for (int j = 0; j < 16; j++){
        if (j < 15) asm volatile("cp.async.wait_group 1;\n");
        else        asm volatile("cp.async.wait_group 0;\n");
        __syncthreads();                 // single barrier per iteration
        const int st = j % 3;
        const __half* Kb = &Ks[st*KBUFH];
        const __half* Vb = &Vs[st*VBUFH];

        // prefetch j+2 into stage (j+2)%3 == (j-1)%3, consumed at iter j-1;
        // the barrier above fences those reads.
        if (j + 2 < 16) loadKV((j+2)%3, j+2);

        // ---- S = Q @ K^T ----
        float s[16][4];
        #pragma unroll
        for (int nf = 0; nf < 16; nf++)
            #pragma unroll
            for (int c = 0; c < 4; c++) s[nf][c] = 0.f;
        #pragma unroll
        for (int nf2 = 0; nf2 < 8; nf2++){
            #pragma unroll
            for (int ks = 0; ks < 4; ks++){
                unsigned kb[4];
                ldsm4(kb, &Kb[(nf2*16 + bqrow)*KSTH + ks*16 + bqcol]);
                mma_f16(s[2*nf2+0], qf[ks], kb[0], kb[1]);
                mma_f16(s[2*nf2+1], qf[ks], kb[2], kb[3]);
            }
        }

        // ---- scale + bias ----
        const float* br0 = Bg + (long)(q0+mrow+g  )*N_ + j*128 + 2*tg;
        const float* br1 = Bg + (long)(q0+mrow+g+8)*N_ + j*128 + 2*tg;
        #pragma unroll
        for (int nf = 0; nf < 16; nf++){
            float2 t0 = *reinterpret_cast<const float2*>(br0 + nf*8);
            float2 t1 = *reinterpret_cast<const float2*>(br1 + nf*8);
            s[nf][0] = fmaf(s[nf][0], 0.125f, t0.x);
            s[nf][1] = fmaf(s[nf][1], 0.125f, t0.y);
            s[nf][2] = fmaf(s[nf][2], 0.125f, t1.x);
            s[nf][3] = fmaf(s[nf][3], 0.125f, t1.y);
        }

        // ---- online softmax ----
        float mt0 = -1e30f, mt1 = -1e30f;
        #pragma unroll
        for (int nf = 0; nf < 16; nf++){
            mt0 = fmaxf(mt0, fmaxf(s[nf][0], s[nf][1]));
            mt1 = fmaxf(mt1, fmaxf(s[nf][2], s[nf][3]));
        }
        mt0 = fmaxf(mt0, __shfl_xor_sync(0xffffffffu, mt0, 1));
        mt0 = fmaxf(mt0, __shfl_xor_sync(0xffffffffu, mt0, 2));
        mt1 = fmaxf(mt1, __shfl_xor_sync(0xffffffffu, mt1, 1));
        mt1 = fmaxf(mt1, __shfl_xor_sync(0xffffffffu, mt1, 2));
        const float mn0 = fmaxf(m0, mt0), mn1 = fmaxf(m1, mt1);
        const float cr0 = __expf(m0 - mn0), cr1 = __expf(m1 - mn1);
        m0 = mn0; m1 = mn1;

        float ls0 = 0.f, ls1 = 0.f;
        __half* pr0 = &Ps[(mrow+g  )*PSTH + 2*tg];
        __half* pr1 = &Ps[(mrow+g+8)*PSTH + 2*tg];
        #pragma unroll
        for (int nf = 0; nf < 16; nf++){
            float p0 = __expf(s[nf][0] - m0);
            float p1 = __expf(s[nf][1] - m0);
            float p2 = __expf(s[nf][2] - m1);
            float p3 = __expf(s[nf][3] - m1);
            ls0 += p0 + p1; ls1 += p2 + p3;
            *reinterpret_cast<unsigned*>(pr0 + nf*8) = pk2(p0, p1);
            *reinterpret_cast<unsigned*>(pr1 + nf*8) = pk2(p2, p3);
        }
        ls0 += __shfl_xor_sync(0xffffffffu, ls0, 1);
        ls0 += __shfl_xor_sync(0xffffffffu, ls0, 2);
        ls1 += __shfl_xor_sync(0xffffffffu, ls1, 1);
        ls1 += __shfl_xor_sync(0xffffffffu, ls1, 2);
        l0 = l0*cr0 + ls0;
        l1 = l1*cr1 + ls1;
        #pragma unroll
        for (int nf = 0; nf < 8; nf++){
            o[nf][0] *= cr0; o[nf][1] *= cr0;
            o[nf][2] *= cr1; o[nf][3] *= cr1;
        }
        __syncwarp();

        // ---- O += P @ V ----
        #pragma unroll
        for (int ks2 = 0; ks2 < 8; ks2++){
            unsigned a[4];
            ldsm4(a, &Ps[(mrow + arow)*PSTH + ks2*16 + acol]);
            #pragma unroll
            for (int nf2 = 0; nf2 < 4; nf2++){
                unsigned vb[4];
                ldsm4(vb, &Vb[(nf2*16 + bqrow)*VSTH + ks2*16 + bqcol]);
                mma_f16(o[2*nf2+0], a, vb[0], vb[1]);
                mma_f16(o[2*nf2+1], a, vb[2], vb[3]);
            }
        }
    }

    // ---- epilogue ----
    const float inv0 = 1.0f / l0, inv1 = 1.0f / l1;
    __half* o0 = ao + (long)(bb*N_ + q0 + mrow + g  )*D_ + hh*DH_ + 2*tg;
    __half* o1 = ao + (long)(bb*N_ + q0 + mrow + g+8)*D_ + hh*DH_ + 2*tg;
    #pragma unroll
    for (int nf = 0; nf < 8; nf++){
        *reinterpret_cast<unsigned*>(o0 + nf*8) = pk2(o[nf][0]*inv0, o[nf][1]*inv0);
        *reinterpret_cast<unsigned*>(o1 + nf*8) = pk2(o[nf][2]*inv1, o[nf][3]*inv1);
    }
}

// ---------------- fp16 tensor-core GEMM (3-stage pipeline) -------------------
#define GSTH 72
#define GSTAGE (2*128*GSTH)            // halves per stage (A+B)
#define GEMM_SMEM (3*GSTAGE*2)

template<bool GELU, bool OUTH>
__global__ void __launch_bounds__(256,2)
gemm_h(const __half* __restrict__ A, const __half* __restrict__ Bt,
       const float* __restrict__ bias, const float* __restrict__ residual,
       void* __restrict__ Cv, int K, int lda, int ldb, int ldc)
{
    extern __shared__ __half smg[];

    const int bm = blockIdx.y * 128;
    const int bn = blockIdx.x * 128;
    const int tid  = threadIdx.x;
    const int wid  = tid >> 5, lane = tid & 31;
    const int wm   = wid >> 2, wn = wid & 3;
    const int g    = lane >> 2, tg = lane & 3;
    const int li = lane >> 3, lr = lane & 7;
    const int arow = (li&1)*8 + lr, acol = (li>>1)*8;
    const int brow = (li>>1)*8 + lr, bcol = (li&1)*8;

    float acc[4][4][4];
    #pragma unroll
    for (int i = 0; i < 4; i++)
        #pragma unroll
        for (int j = 0; j < 4; j++)
            #pragma unroll
            for (int c = 0; c < 4; c++) acc[i][j][c] = 0.f;

    auto issue = [&](int st, int k0){
        __half* As = smg + st*GSTAGE;
        __half* Bs = As + 128*GSTH;
        #pragma unroll
        for (int it = 0; it < 4; it++){
            int i = tid + it*256;
            int r = i >> 3, c8 = (i & 7)*8;
            cpa16(&As[r*GSTH + c8], &A [(long)(bm+r)*lda + k0 + c8]);
        }
        #pragma unroll
        for (int it = 0; it < 4; it++){
            int i = tid + it*256;
            int r = i >> 3, c8 = (i & 7)*8;
            cpa16(&Bs[r*GSTH + c8], &Bt[(long)(bn+r)*ldb + k0 + c8]);
        }
        asm volatile("cp.async.commit_group;\n");
    };

    const int nIter = K / 64;            // >= 2 for all our shapes
    issue(0, 0);
    issue(1, 64);

    for (int it = 0; it < nIter; it++){
        if (it < nIter-1) asm volatile("cp.async.wait_group 1;\n");
        else              asm volatile("cp.async.wait_group 0;\n");
        __syncthreads();                 // single barrier per iteration
        const int st = it % 3;
        const __half* Ab = smg + st*GSTAGE;
        const __half* Bb = Ab + 128*GSTH;

        if (it + 2 < nIter) issue((it+2)%3, (it+2)*64);

        #pragma unroll
        for (int ks = 0; ks < 4; ks++){
            unsigned a[4][4], b[2][4];
            #pragma unroll
            for (int mf = 0; mf < 4; mf++)
                ldsm4(a[mf], &Ab[(wm*64 + mf*16 + arow)*GSTH + ks*16 + acol]);
            #pragma unroll
            for (int nf2 = 0; nf2 < 2; nf2++)
                ldsm4(b[nf2], &Bb[(wn*32 + nf2*16 + brow)*GSTH + ks*16 + bcol]);
            #pragma unroll
            for (int mf = 0; mf < 4; mf++){
                #pragma unroll
                for (int nf2 = 0; nf2 < 2; nf2++){
                    mma_f16(acc[mf][2*nf2+0], a[mf], b[nf2][0], b[nf2][1]);
                    mma_f16(acc[mf][2*nf2+1], a[mf], b[nf2][2], b[nf2][3]);
                }
            }
        }
    }

    #pragma unroll
    for (int mf = 0; mf < 4; mf++){
        #pragma unroll
        for (int nf = 0; nf < 4; nf++){
            const int col = bn + wn*32 + nf*8 + tg*2;
            #pragma unroll
            for (int h = 0; h < 2; h++){
                const int row = bm + wm*64 + mf*16 + g + h*8;
                float v0 = acc[mf][nf][h*2+0];
                float v1 = acc[mf][nf][h*2+1];
                if (bias){ v0 += bias[col]; v1 += bias[col+1]; }
                if (GELU){
                    v0 = 0.5f*v0*(1.0f + erff(v0*0.70710678118654752f));
                    v1 = 0.5f*v1*(1.0f + erff(v1*0.70710678118654752f));
                }
                if (residual){
                    v0 += residual[(long)row*ldc + col];
                    v1 += residual[(long)row*ldc + col + 1];
                }
                if (OUTH){
                    *reinterpret_cast<unsigned*>((__half*)Cv + (long)row*ldc + col) = pk2(v0, v1);
                } else {
                    *reinterpret_cast<float2*>((float*)Cv + (long)row*ldc + col) = make_float2(v0, v1);
                }
            }
        }
    }
}

// ---------------------------------------------------------------------------
extern "C" void kernel_launch(void* const* d_in, const int* in_sizes, int n_in,
                              void* d_out, int out_size)
{
    const float* x      = (const float*)d_in[0];
    const float* Wqkv   = (const float*)d_in[1];
    const float* Wout   = (const float*)d_in[2];
    const float* gamma1 = (const float*)d_in[3];
    const float* beta1  = (const float*)d_in[4];
    const float* gamma2 = (const float*)d_in[5];
    const float* beta2  = (const float*)d_in[6];
    const float* W1     = (const float*)d_in[7];
    const float* b1     = (const float*)d_in[8];
    const float* W2     = (const float*)d_in[9];
    const float* b2     = (const float*)d_in[10];
    const float* abias  = (const float*)d_in[11];
    float* out = (float*)d_out;

    __half *h, *qkv, *vt, *ao, *ffn, *wqkvT, *woutT, *w1T, *w2T;
    float *x1;
    cudaGetSymbolAddress((void**)&h,     g_h);
    cudaGetSymbolAddress((void**)&qkv,   g_qkv);
    cudaGetSymbolAddress((void**)&vt,    g_vt);
    cudaGetSymbolAddress((void**)&ao,    g_ao);
    cudaGetSymbolAddress((void**)&x1,    g_x1);
    cudaGetSymbolAddress((void**)&ffn,   g_ffn);
    cudaGetSymbolAddress((void**)&wqkvT, g_wqkvT);
    cudaGetSymbolAddress((void**)&woutT, g_woutT);
    cudaGetSymbolAddress((void**)&w1T,   g_w1T);
    cudaGetSymbolAddress((void**)&w2T,   g_w2T);

    cudaFuncSetAttribute(flash_kernel, cudaFuncAttributeMaxDynamicSharedMemorySize, FA_SMEM);
    cudaFuncSetAttribute(gemm_h<false,true>,  cudaFuncAttributeMaxDynamicSharedMemorySize, GEMM_SMEM);
    cudaFuncSetAttribute(gemm_h<false,false>, cudaFuncAttributeMaxDynamicSharedMemorySize, GEMM_SMEM);
    cudaFuncSetAttribute(gemm_h<true,true>,   cudaFuncAttributeMaxDynamicSharedMemorySize, GEMM_SMEM);

    // 0. weights -> fp16 transposed
    convT<<<dim3(QKVC/32, D_/32), dim3(32,8)>>>(Wqkv, wqkvT, D_, QKVC);
    convT<<<dim3(D_/32,   D_/32), dim3(32,8)>>>(Wout, woutT, D_, D_);
    convT<<<dim3(M_/32,   D_/32), dim3(32,8)>>>(W1,   w1T,   D_, M_);
    convT<<<dim3(D_/32,   M_/32), dim3(32,8)>>>(W2,   w2T,   M_, D_);

    // 1. h = LN(x)
    ln_kernel<<<R_, 256>>>(x, gamma1, beta1, h);

    // 2. qkv = h @ Wqkv  (fp16 out)
    gemm_h<false,true><<<dim3(QKVC/128, R_/128), 256, GEMM_SMEM>>>(
        h, wqkvT, nullptr, nullptr, qkv, D_, D_, D_, QKVC);

    // 2b. vt = V transposed per head
    vtrans<<<dim3(N_/32, 2*H_*B_), dim3(32,8)>>>(qkv, vt);

    // 3-5. flash attention -> ao (fp16)
    flash_kernel<<<dim3(N_/128, H_, B_), 256, FA_SMEM>>>(qkv, vt, abias, ao);

    // 6. x1 = ao @ Wout + x  (fp32 out)
    gemm_h<false,false><<<dim3(D_/128, R_/128), 256, GEMM_SMEM>>>(
        ao, woutT, nullptr, x, x1, D_, D_, D_, D_);

    // 7. h = LN(x1)
    ln_kernel<<<R_, 256>>>(x1, gamma2, beta2, h);

    // 8. ffn = gelu(h @ W1 + b1)  (fp16 out)
    gemm_h<true,true><<<dim3(M_/128, R_/128), 256, GEMM_SMEM>>>(
        h, w1T, b1, nullptr, ffn, D_, D_, D_, M_);

    // 9. out = ffn @ W2 + b2 + x1  (fp32 out)
    gemm_h<false,false><<<dim3(D_/128, R_/128), 256, GEMM_SMEM>>>(
        ffn, w2T, b2, x1, out, M_, M_, M_, D_);
}